// round 2
// baseline (speedup 1.0000x reference)
#include <cuda_runtime.h>
#include <math.h>

// ----------------------------------------------------------------------------
// ConformerBlock: B=4, T=1024, D=512, H=8, DH=64, W1=32, WB=65, FF=2048,
// CE=1024, KS=31. All fp32.
//   h  = x + 0.5*FF1(x)
//   h += longformer_attn(h)   (also emits probs)
//   h += conv_module(h)
//   h += 0.5*FF2(h)
//   out = LN(h)
// ----------------------------------------------------------------------------

#define NTOK   4096          // B*T
#define DMODEL 512
#define TSEQ   1024
#define NHEAD  8
#define DHEAD  64
#define WB     65
#define FFDIM  2048
#define CEDIM  1024
#define KSIZE  31
#define OUT_ELEMS   (NTOK * DMODEL)          // 2097152
#define PROB_ELEMS  (NTOK * NHEAD * WB)      // 2129920

// ---- scratch (static device memory; no allocations allowed) ----
__device__ __align__(16) float g_xn[NTOK * DMODEL];
__device__ __align__(16) float g_h [NTOK * DMODEL];
__device__ __align__(16) float g_ff[NTOK * FFDIM];
__device__ __align__(16) float g_q [NTOK * DMODEL];
__device__ __align__(16) float g_k [NTOK * DMODEL];
__device__ __align__(16) float g_v [NTOK * DMODEL];
__device__ __align__(16) float g_cg[NTOK * CEDIM];
__device__ __align__(16) float g_ca[NTOK * DMODEL];
__device__ __align__(16) float g_cv[NTOK * DMODEL];
__device__ __align__(16) float g_probs_spill[PROB_ELEMS];   // fallback if d_out lacks probs

// ---------------------------------------------------------------- helpers
__device__ __forceinline__ float warp_sum(float v) {
    #pragma unroll
    for (int o = 16; o > 0; o >>= 1) v += __shfl_xor_sync(0xffffffffu, v, o);
    return v;
}
__device__ __forceinline__ float warp_max(float v) {
    #pragma unroll
    for (int o = 16; o > 0; o >>= 1) v = fmaxf(v, __shfl_xor_sync(0xffffffffu, v, o));
    return v;
}
__device__ __forceinline__ float swishf(float x) {
    return x / (1.0f + expf(-x));
}

// ---------------------------------------------------------------- LayerNorm
// one block per row (512 elems), 256 threads, 2 elems/thread
__global__ void ln_kernel(const float* __restrict__ x,
                          const float* __restrict__ g,
                          const float* __restrict__ b,
                          float* __restrict__ out) {
    int row = blockIdx.x;
    int tid = threadIdx.x;
    const float* xr = x + (size_t)row * DMODEL;
    float v0 = xr[tid], v1 = xr[tid + 256];
    float s = v0 + v1;
    float q = v0 * v0 + v1 * v1;
    s = warp_sum(s);
    q = warp_sum(q);
    __shared__ float sh[16];
    int w = tid >> 5, l = tid & 31;
    if (l == 0) { sh[w] = s; sh[w + 8] = q; }
    __syncthreads();
    if (w == 0) {
        float a = (l < 8) ? sh[l] : 0.0f;
        float c = (l < 8) ? sh[l + 8] : 0.0f;
        a = warp_sum(a);
        c = warp_sum(c);
        if (l == 0) { sh[0] = a; sh[1] = c; }
    }
    __syncthreads();
    float mean = sh[0] * (1.0f / DMODEL);
    float var  = sh[1] * (1.0f / DMODEL) - mean * mean;
    float inv  = rsqrtf(var + 1e-5f);
    float* orow = out + (size_t)row * DMODEL;
    orow[tid]       = (v0 - mean) * inv * g[tid]       + b[tid];
    orow[tid + 256] = (v1 - mean) * inv * g[tid + 256] + b[tid + 256];
}

// ---------------------------------------------------------------- GEMM
// C[M,N] = epilogue(A[M,K] @ B[K,N] + bias[N])
// MODE 0: bias only     MODE 1: swish(.)     MODE 2: res + scale*(.)
// All of M,N divisible by 128, K by 8. 256 threads, 128x128 tile, 8x8 micro.
template <int MODE>
__global__ __launch_bounds__(256)
void gemm128(const float* __restrict__ A, const float* __restrict__ B,
             const float* __restrict__ bias, const float* __restrict__ res,
             float scale, float* __restrict__ C, int M, int N, int K) {
    __shared__ __align__(16) float As[8][128];
    __shared__ __align__(16) float Bs[8][128];

    int tid = threadIdx.x;
    int bm = blockIdx.y * 128;
    int bn = blockIdx.x * 128;

    float acc[8][8];
    #pragma unroll
    for (int i = 0; i < 8; i++)
        #pragma unroll
        for (int j = 0; j < 8; j++) acc[i][j] = 0.0f;

    int aRow = tid >> 1;            // 0..127
    int aCol = (tid & 1) * 4;       // 0 or 4
    int bRow = tid >> 5;            // 0..7
    int bCol = (tid & 31) * 4;      // 0..124

    const float* Aptr = A + (size_t)(bm + aRow) * K + aCol;
    const float* Bptr = B + (size_t)bRow * N + bn + bCol;

    int rb = (tid >> 4) * 8;        // 0..120
    int cb = (tid & 15) * 8;        // 0..120

    for (int k0 = 0; k0 < K; k0 += 8) {
        float4 av = *reinterpret_cast<const float4*>(Aptr + k0);
        As[aCol + 0][aRow] = av.x;
        As[aCol + 1][aRow] = av.y;
        As[aCol + 2][aRow] = av.z;
        As[aCol + 3][aRow] = av.w;
        float4 bv = *reinterpret_cast<const float4*>(Bptr + (size_t)k0 * N);
        *reinterpret_cast<float4*>(&Bs[bRow][bCol]) = bv;
        __syncthreads();

        #pragma unroll
        for (int k = 0; k < 8; k++) {
            float ar[8], br[8];
            *reinterpret_cast<float4*>(&ar[0]) = *reinterpret_cast<const float4*>(&As[k][rb]);
            *reinterpret_cast<float4*>(&ar[4]) = *reinterpret_cast<const float4*>(&As[k][rb + 4]);
            *reinterpret_cast<float4*>(&br[0]) = *reinterpret_cast<const float4*>(&Bs[k][cb]);
            *reinterpret_cast<float4*>(&br[4]) = *reinterpret_cast<const float4*>(&Bs[k][cb + 4]);
            #pragma unroll
            for (int i = 0; i < 8; i++)
                #pragma unroll
                for (int j = 0; j < 8; j++)
                    acc[i][j] = fmaf(ar[i], br[j], acc[i][j]);
        }
        __syncthreads();
    }

    #pragma unroll
    for (int i = 0; i < 8; i++) {
        int row = bm + rb + i;
        float* crow = C + (size_t)row * N;
        const float* rrow = (MODE == 2) ? (res + (size_t)row * N) : nullptr;
        #pragma unroll
        for (int j = 0; j < 8; j++) {
            int col = bn + cb + j;
            float vv = acc[i][j] + bias[col];
            if (MODE == 1) vv = swishf(vv);
            if (MODE == 2) vv = rrow[col] + scale * vv;
            crow[col] = vv;
        }
    }
}

// ---------------------------------------------------------------- attention
// one block per token (row), 8 warps = 8 heads. q already includes bias;
// the 1/sqrt(DH)=0.125 scale is applied on q load.
__global__ __launch_bounds__(256)
void attn_kernel(const float* __restrict__ q, const float* __restrict__ k,
                 const float* __restrict__ v, float* __restrict__ h,
                 float* __restrict__ probs) {
    int row = blockIdx.x;             // 0..4095
    int t = row & (TSEQ - 1);
    int bstart = row - t;             // b*T
    int head = threadIdx.x >> 5;
    int lane = threadIdx.x & 31;
    int d0 = lane * 2;
    int base = row * DMODEL + head * DHEAD;

    float q0 = q[base + d0] * 0.125f;
    float q1 = q[base + d0 + 1] * 0.125f;

    __shared__ float sc[NHEAD][WB + 3];
    float* scrow = sc[head];

    for (int w = 0; w < WB; w++) {
        int pos = t + w - 32;
        float s = -1e9f;
        if (pos >= 0 && pos < TSEQ) {
            int kb = (bstart + pos) * DMODEL + head * DHEAD + d0;
            float p = q0 * k[kb] + q1 * k[kb + 1];
            p = warp_sum(p);
            s = p;
        }
        if (lane == 0) scrow[w] = s;
    }
    __syncwarp();

    float m = -1e9f;
    for (int w = lane; w < WB; w += 32) m = fmaxf(m, scrow[w]);
    m = warp_max(m);

    float sum = 0.0f;
    for (int w = lane; w < WB; w += 32) {
        float e = expf(scrow[w] - m);
        scrow[w] = e;
        sum += e;
    }
    sum = warp_sum(sum);
    float inv = 1.0f / sum;

    float* prow = probs + ((size_t)row * NHEAD + head) * WB;
    for (int w = lane; w < WB; w += 32) {
        float pr = scrow[w] * inv;
        scrow[w] = pr;
        prow[w] = pr;
    }
    __syncwarp();

    float a0 = 0.0f, a1 = 0.0f;
    for (int w = 0; w < WB; w++) {
        int pos = t + w - 32;
        if (pos >= 0 && pos < TSEQ) {
            float pr = scrow[w];
            int vb = (bstart + pos) * DMODEL + head * DHEAD + d0;
            a0 = fmaf(pr, v[vb], a0);
            a1 = fmaf(pr, v[vb + 1], a1);
        }
    }
    h[base + d0]     += a0;
    h[base + d0 + 1] += a1;
}

// ---------------------------------------------------------------- GLU
__global__ void glu_kernel(const float* __restrict__ cg, float* __restrict__ ca) {
    int idx = blockIdx.x * blockDim.x + threadIdx.x;   // NTOK*DMODEL
    int d = idx & (DMODEL - 1);
    int row = idx >> 9;
    float a = cg[(size_t)row * CEDIM + d];
    float gate = cg[(size_t)row * CEDIM + DMODEL + d];
    ca[idx] = a / (1.0f + expf(-gate));   // a * sigmoid(gate)
}

// ------------------------------------------------------- depthwise conv + BN + swish
__global__ void dwconv_kernel(const float* __restrict__ ca,
                              const float* __restrict__ dw_w,
                              const float* __restrict__ dw_b,
                              const float* __restrict__ bn_g,
                              const float* __restrict__ bn_b,
                              float* __restrict__ out) {
    int idx = blockIdx.x * blockDim.x + threadIdx.x;   // NTOK*DMODEL
    int d = idx & (DMODEL - 1);
    int row = idx >> 9;
    int t = row & (TSEQ - 1);
    int bstart = row - t;
    float acc = 0.0f;
    #pragma unroll
    for (int j = 0; j < KSIZE; j++) {
        int pos = t + j - 15;
        if (pos >= 0 && pos < TSEQ)
            acc = fmaf(ca[(size_t)(bstart + pos) * DMODEL + d], dw_w[j * DMODEL + d], acc);
    }
    acc += dw_b[d];
    float hx = acc * rsqrtf(1.0f + 1e-5f) * bn_g[d] + bn_b[d];
    out[idx] = swishf(hx);
}

// ---------------------------------------------------------------- launch
static inline dim3 gemm_grid(int M, int N) { return dim3(N / 128, M / 128); }

extern "C" void kernel_launch(void* const* d_in, const int* in_sizes, int n_in,
                              void* d_out, int out_size) {
    const float* x          = (const float*)d_in[0];
    const float* ff1_ln_g   = (const float*)d_in[1];
    const float* ff1_ln_b   = (const float*)d_in[2];
    const float* ff1_w1     = (const float*)d_in[3];
    const float* ff1_b1     = (const float*)d_in[4];
    const float* ff1_w2     = (const float*)d_in[5];
    const float* ff1_b2     = (const float*)d_in[6];
    const float* ff2_ln_g   = (const float*)d_in[7];
    const float* ff2_ln_b   = (const float*)d_in[8];
    const float* ff2_w1     = (const float*)d_in[9];
    const float* ff2_b1     = (const float*)d_in[10];
    const float* ff2_w2     = (const float*)d_in[11];
    const float* ff2_b2     = (const float*)d_in[12];
    const float* wq         = (const float*)d_in[13];
    const float* bq         = (const float*)d_in[14];
    const float* wk         = (const float*)d_in[15];
    const float* bk         = (const float*)d_in[16];
    const float* wv         = (const float*)d_in[17];
    const float* bv         = (const float*)d_in[18];
    const float* conv_ln_g  = (const float*)d_in[19];
    const float* conv_ln_b  = (const float*)d_in[20];
    const float* conv_pw1_w = (const float*)d_in[21];
    const float* conv_pw1_b = (const float*)d_in[22];
    const float* conv_dw_w  = (const float*)d_in[23];
    const float* conv_dw_b  = (const float*)d_in[24];
    const float* conv_bn_g  = (const float*)d_in[25];
    const float* conv_bn_b  = (const float*)d_in[26];
    const float* conv_pw2_w = (const float*)d_in[27];
    const float* conv_pw2_b = (const float*)d_in[28];
    const float* final_ln_g = (const float*)d_in[29];
    const float* final_ln_b = (const float*)d_in[30];

    // resolve scratch (host-side symbol lookups; not stream ops, capture-safe)
    float *xn, *h, *ff, *q, *k, *v, *cg, *ca, *cv, *pspill;
    cudaGetSymbolAddress((void**)&xn, g_xn);
    cudaGetSymbolAddress((void**)&h,  g_h);
    cudaGetSymbolAddress((void**)&ff, g_ff);
    cudaGetSymbolAddress((void**)&q,  g_q);
    cudaGetSymbolAddress((void**)&k,  g_k);
    cudaGetSymbolAddress((void**)&v,  g_v);
    cudaGetSymbolAddress((void**)&cg, g_cg);
    cudaGetSymbolAddress((void**)&ca, g_ca);
    cudaGetSymbolAddress((void**)&cv, g_cv);
    cudaGetSymbolAddress((void**)&pspill, g_probs_spill);

    float* out_main  = (float*)d_out;
    // probs is the second tuple output; only write into d_out if it has room.
    float* out_probs = (out_size >= OUT_ELEMS + PROB_ELEMS)
                         ? (float*)d_out + OUT_ELEMS : pspill;

    // ---- FF1: h = x + 0.5 * (swish(LN(x)@w1+b1) @ w2 + b2)
    ln_kernel<<<NTOK, 256>>>(x, ff1_ln_g, ff1_ln_b, xn);
    gemm128<1><<<gemm_grid(NTOK, FFDIM), 256>>>(xn, ff1_w1, ff1_b1, nullptr, 0.f,
                                                ff, NTOK, FFDIM, DMODEL);
    gemm128<2><<<gemm_grid(NTOK, DMODEL), 256>>>(ff, ff1_w2, ff1_b2, x, 0.5f,
                                                 h, NTOK, DMODEL, FFDIM);

    // ---- attention: q/k/v = h@W + b ; h += ctx ; probs out
    gemm128<0><<<gemm_grid(NTOK, DMODEL), 256>>>(h, wq, bq, nullptr, 0.f,
                                                 q, NTOK, DMODEL, DMODEL);
    gemm128<0><<<gemm_grid(NTOK, DMODEL), 256>>>(h, wk, bk, nullptr, 0.f,
                                                 k, NTOK, DMODEL, DMODEL);
    gemm128<0><<<gemm_grid(NTOK, DMODEL), 256>>>(h, wv, bv, nullptr, 0.f,
                                                 v, NTOK, DMODEL, DMODEL);
    attn_kernel<<<NTOK, 256>>>(q, k, v, h, out_probs);

    // ---- conv module: h += pw2(swish(bn(dwconv(glu(pw1(LN(h)))))))
    ln_kernel<<<NTOK, 256>>>(h, conv_ln_g, conv_ln_b, xn);
    gemm128<0><<<gemm_grid(NTOK, CEDIM), 256>>>(xn, conv_pw1_w, conv_pw1_b, nullptr, 0.f,
                                                cg, NTOK, CEDIM, DMODEL);
    glu_kernel<<<(NTOK * DMODEL) / 256, 256>>>(cg, ca);
    dwconv_kernel<<<(NTOK * DMODEL) / 256, 256>>>(ca, conv_dw_w, conv_dw_b,
                                                  conv_bn_g, conv_bn_b, cv);
    gemm128<2><<<gemm_grid(NTOK, DMODEL), 256>>>(cv, conv_pw2_w, conv_pw2_b, h, 1.0f,
                                                 h, NTOK, DMODEL, DMODEL);

    // ---- FF2: h = h + 0.5 * (swish(LN(h)@w1+b1) @ w2 + b2)
    ln_kernel<<<NTOK, 256>>>(h, ff2_ln_g, ff2_ln_b, xn);
    gemm128<1><<<gemm_grid(NTOK, FFDIM), 256>>>(xn, ff2_w1, ff2_b1, nullptr, 0.f,
                                                ff, NTOK, FFDIM, DMODEL);
    gemm128<2><<<gemm_grid(NTOK, DMODEL), 256>>>(ff, ff2_w2, ff2_b2, h, 0.5f,
                                                 h, NTOK, DMODEL, FFDIM);

    // ---- final LN -> out
    ln_kernel<<<NTOK, 256>>>(h, final_ln_g, final_ln_b, out_main);
}

// round 4
// speedup vs baseline: 2.4406x; 2.4406x over previous
#include <cuda_runtime.h>
#include <math.h>
#include <stdint.h>

// ----------------------------------------------------------------------------
// ConformerBlock: B=4, T=1024, D=512, H=8, DH=64, W1=32, WB=65, FF=2048,
// CE=1024, KS=31.
//   h  = x + 0.5*FF1(x)
//   h += longformer_attn(h)   (also emits probs)
//   h += conv_module(h)
//   h += 0.5*FF2(h)
//   out = LN(h)
// GEMMs in tf32 mma.sync (fp32 accumulate), everything else fp32.
// ----------------------------------------------------------------------------

#define NTOK   4096          // B*T
#define DMODEL 512
#define TSEQ   1024
#define NHEAD  8
#define DHEAD  64
#define WB     65
#define FFDIM  2048
#define CEDIM  1024
#define KSIZE  31
#define OUT_ELEMS   (NTOK * DMODEL)          // 2097152
#define PROB_ELEMS  (NTOK * NHEAD * WB)      // 2129920

// ---- scratch (static device memory; no allocations allowed) ----
__device__ __align__(16) float g_xn[NTOK * DMODEL];
__device__ __align__(16) float g_h [NTOK * DMODEL];
__device__ __align__(16) float g_ff[NTOK * FFDIM];
__device__ __align__(16) float g_q [NTOK * DMODEL];
__device__ __align__(16) float g_k [NTOK * DMODEL];
__device__ __align__(16) float g_v [NTOK * DMODEL];
__device__ __align__(16) float g_cg[NTOK * CEDIM];
__device__ __align__(16) float g_ca[NTOK * DMODEL];
__device__ __align__(16) float g_cv[NTOK * DMODEL];
__device__ __align__(16) float g_probs_spill[PROB_ELEMS];

// ---------------------------------------------------------------- helpers
__device__ __forceinline__ float warp_sum(float v) {
    #pragma unroll
    for (int o = 16; o > 0; o >>= 1) v += __shfl_xor_sync(0xffffffffu, v, o);
    return v;
}
__device__ __forceinline__ float warp_max(float v) {
    #pragma unroll
    for (int o = 16; o > 0; o >>= 1) v = fmaxf(v, __shfl_xor_sync(0xffffffffu, v, o));
    return v;
}
__device__ __forceinline__ float swishf(float x) {
    return x / (1.0f + expf(-x));
}
__device__ __forceinline__ uint32_t f2tf32(float f) {
    uint32_t r;
    asm("cvt.rna.tf32.f32 %0, %1;" : "=r"(r) : "f"(f));
    return r;
}
__device__ __forceinline__ void mma_tf32(float c[4], const uint32_t a[4], const uint32_t b[2]) {
    asm volatile(
        "mma.sync.aligned.m16n8k8.row.col.f32.tf32.tf32.f32 "
        "{%0,%1,%2,%3}, {%4,%5,%6,%7}, {%8,%9}, {%0,%1,%2,%3};"
        : "+f"(c[0]), "+f"(c[1]), "+f"(c[2]), "+f"(c[3])
        : "r"(a[0]), "r"(a[1]), "r"(a[2]), "r"(a[3]), "r"(b[0]), "r"(b[1]));
}

// ---------------------------------------------------------------- tf32 GEMM
// C[M,N] = epilogue(A[M,K] @ B[K,N] + bias[N])
// MODE 0: bias only     MODE 1: swish(.)     MODE 2: res + scale*(.)
// 128x128 CTA tile, BK=16, 256 threads (8 warps, 4x2), warp does 32x64.
template <int MODE>
__device__ __forceinline__
void gemm_body(const float* __restrict__ A, const float* __restrict__ Bm,
               const float* __restrict__ bias, const float* __restrict__ res,
               float scale, float* __restrict__ C,
               int M, int N, int K, int bm, int bn) {
    __shared__ __align__(16) uint32_t As[128][20];   // padded: stride 20 words
    __shared__ __align__(16) uint32_t Bs[16][128];   // XOR-swizzled columns

    int tid  = threadIdx.x;
    int lane = tid & 31, wid = tid >> 5;
    int g = lane >> 2, tg = lane & 3;
    int m0w = (wid >> 1) * 32;
    int n0w = (wid & 1) * 64;

    // global load mapping
    int arow = tid >> 1, acol = (tid & 1) * 8;       // A: 128 rows x 16 cols
    int brow = tid >> 4, bcol = (tid & 15) * 8;      // B: 16 rows x 128 cols
    const float* Ap = A + (size_t)(bm + arow) * K + acol;
    const float* Bp = Bm + (size_t)brow * N + bn + bcol;
    int bswz = bcol ^ ((brow & 3) * 8);

    float acc[2][8][4];
    #pragma unroll
    for (int mt = 0; mt < 2; mt++)
        #pragma unroll
        for (int nt = 0; nt < 8; nt++)
            #pragma unroll
            for (int i = 0; i < 4; i++) acc[mt][nt][i] = 0.0f;

    float4 pa0, pa1, pb0, pb1;
    // preload tile 0
    pa0 = *(const float4*)(Ap);
    pa1 = *(const float4*)(Ap + 4);
    pb0 = *(const float4*)(Bp);
    pb1 = *(const float4*)(Bp + 4);

    for (int k0 = 0; k0 < K; k0 += 16) {
        // store prefetched tile to smem (cvt to tf32)
        {
            uint4 t;
            t.x = f2tf32(pa0.x); t.y = f2tf32(pa0.y); t.z = f2tf32(pa0.z); t.w = f2tf32(pa0.w);
            *(uint4*)&As[arow][acol] = t;
            t.x = f2tf32(pa1.x); t.y = f2tf32(pa1.y); t.z = f2tf32(pa1.z); t.w = f2tf32(pa1.w);
            *(uint4*)&As[arow][acol + 4] = t;
            t.x = f2tf32(pb0.x); t.y = f2tf32(pb0.y); t.z = f2tf32(pb0.z); t.w = f2tf32(pb0.w);
            *(uint4*)&Bs[brow][bswz] = t;
            t.x = f2tf32(pb1.x); t.y = f2tf32(pb1.y); t.z = f2tf32(pb1.z); t.w = f2tf32(pb1.w);
            *(uint4*)&Bs[brow][bswz + 4] = t;
        }
        __syncthreads();

        int kn = k0 + 16;
        if (kn < K) {   // prefetch next tile
            pa0 = *(const float4*)(Ap + kn);
            pa1 = *(const float4*)(Ap + kn + 4);
            pb0 = *(const float4*)(Bp + (size_t)kn * N);
            pb1 = *(const float4*)(Bp + (size_t)kn * N + 4);
        }

        #pragma unroll
        for (int kk = 0; kk < 16; kk += 8) {
            uint32_t af[2][4], bf[8][2];
            #pragma unroll
            for (int mt = 0; mt < 2; mt++) {
                int r0 = m0w + mt * 16 + g;
                af[mt][0] = As[r0][kk + tg];
                af[mt][1] = As[r0 + 8][kk + tg];
                af[mt][2] = As[r0][kk + tg + 4];
                af[mt][3] = As[r0 + 8][kk + tg + 4];
            }
            #pragma unroll
            for (int nt = 0; nt < 8; nt++) {
                int cs = (n0w + nt * 8 + g) ^ (tg * 8);
                bf[nt][0] = Bs[kk + tg][cs];
                bf[nt][1] = Bs[kk + tg + 4][cs];
            }
            #pragma unroll
            for (int mt = 0; mt < 2; mt++)
                #pragma unroll
                for (int nt = 0; nt < 8; nt++)
                    mma_tf32(acc[mt][nt], af[mt], bf[nt]);
        }
        __syncthreads();
    }

    // epilogue
    #pragma unroll
    for (int mt = 0; mt < 2; mt++) {
        int row0 = bm + m0w + mt * 16 + g;
        #pragma unroll
        for (int nt = 0; nt < 8; nt++) {
            int col = bn + n0w + nt * 8 + tg * 2;
            float bb0 = bias[col], bb1 = bias[col + 1];
            float v0 = acc[mt][nt][0] + bb0;
            float v1 = acc[mt][nt][1] + bb1;
            float v2 = acc[mt][nt][2] + bb0;
            float v3 = acc[mt][nt][3] + bb1;
            if (MODE == 1) {
                v0 = swishf(v0); v1 = swishf(v1); v2 = swishf(v2); v3 = swishf(v3);
            }
            if (MODE == 2) {
                const float* r0p = res + (size_t)row0 * N + col;
                const float* r1p = res + (size_t)(row0 + 8) * N + col;
                v0 = r0p[0] + scale * v0;
                v1 = r0p[1] + scale * v1;
                v2 = r1p[0] + scale * v2;
                v3 = r1p[1] + scale * v3;
            }
            *(float2*)(C + (size_t)row0 * N + col)       = make_float2(v0, v1);
            *(float2*)(C + (size_t)(row0 + 8) * N + col) = make_float2(v2, v3);
        }
    }
}

template <int MODE>
__global__ __launch_bounds__(256, 2)
void gemm_tf32(const float* __restrict__ A, const float* __restrict__ B,
               const float* __restrict__ bias, const float* __restrict__ res,
               float scale, float* __restrict__ C, int M, int N, int K) {
    gemm_body<MODE>(A, B, bias, res, scale, C, M, N, K,
                    blockIdx.y * 128, blockIdx.x * 128);
}

struct QKVArgs {
    const float* w[3];
    const float* b[3];
    float* o[3];
};

__global__ __launch_bounds__(256, 2)
void gemm_tf32_qkv(QKVArgs args, const float* __restrict__ A, int M, int N, int K) {
    int z = blockIdx.z;
    gemm_body<0>(A, args.w[z], args.b[z], nullptr, 0.0f, args.o[z],
                 M, N, K, blockIdx.y * 128, blockIdx.x * 128);
}

// ---------------------------------------------------------------- LayerNorm
__global__ void ln_kernel(const float* __restrict__ x,
                          const float* __restrict__ g,
                          const float* __restrict__ b,
                          float* __restrict__ out) {
    int row = blockIdx.x;
    int tid = threadIdx.x;
    const float* xr = x + (size_t)row * DMODEL;
    float v0 = xr[tid], v1 = xr[tid + 256];
    float s = v0 + v1;
    float q = v0 * v0 + v1 * v1;
    s = warp_sum(s);
    q = warp_sum(q);
    __shared__ float sh[16];
    int w = tid >> 5, l = tid & 31;
    if (l == 0) { sh[w] = s; sh[w + 8] = q; }
    __syncthreads();
    if (w == 0) {
        float a = (l < 8) ? sh[l] : 0.0f;
        float c = (l < 8) ? sh[l + 8] : 0.0f;
        a = warp_sum(a);
        c = warp_sum(c);
        if (l == 0) { sh[0] = a; sh[1] = c; }
    }
    __syncthreads();
    float mean = sh[0] * (1.0f / DMODEL);
    float var  = sh[1] * (1.0f / DMODEL) - mean * mean;
    float inv  = rsqrtf(var + 1e-5f);
    float* orow = out + (size_t)row * DMODEL;
    orow[tid]       = (v0 - mean) * inv * g[tid]       + b[tid];
    orow[tid + 256] = (v1 - mean) * inv * g[tid + 256] + b[tid + 256];
}

// ---------------------------------------------------------------- attention
__global__ __launch_bounds__(256)
void attn_kernel(const float* __restrict__ q, const float* __restrict__ k,
                 const float* __restrict__ v, float* __restrict__ h,
                 float* __restrict__ probs) {
    int row = blockIdx.x;             // 0..4095
    int t = row & (TSEQ - 1);
    int bstart = row - t;             // b*T
    int head = threadIdx.x >> 5;
    int lane = threadIdx.x & 31;
    int d0 = lane * 2;
    int base = row * DMODEL + head * DHEAD;

    float q0 = q[base + d0] * 0.125f;
    float q1 = q[base + d0 + 1] * 0.125f;

    __shared__ float sc[NHEAD][WB + 3];
    float* scrow = sc[head];

    for (int w = 0; w < WB; w++) {
        int pos = t + w - 32;
        float s = -1e9f;
        if (pos >= 0 && pos < TSEQ) {
            int kb = (bstart + pos) * DMODEL + head * DHEAD + d0;
            float p = q0 * k[kb] + q1 * k[kb + 1];
            p = warp_sum(p);
            s = p;
        }
        if (lane == 0) scrow[w] = s;
    }
    __syncwarp();

    float m = -1e9f;
    for (int w = lane; w < WB; w += 32) m = fmaxf(m, scrow[w]);
    m = warp_max(m);

    float sum = 0.0f;
    for (int w = lane; w < WB; w += 32) {
        float e = expf(scrow[w] - m);
        scrow[w] = e;
        sum += e;
    }
    sum = warp_sum(sum);
    float inv = 1.0f / sum;

    float* prow = probs + ((size_t)row * NHEAD + head) * WB;
    for (int w = lane; w < WB; w += 32) {
        float pr = scrow[w] * inv;
        scrow[w] = pr;
        prow[w] = pr;
    }
    __syncwarp();

    float a0 = 0.0f, a1 = 0.0f;
    for (int w = 0; w < WB; w++) {
        int pos = t + w - 32;
        if (pos >= 0 && pos < TSEQ) {
            float pr = scrow[w];
            int vb = (bstart + pos) * DMODEL + head * DHEAD + d0;
            a0 = fmaf(pr, v[vb], a0);
            a1 = fmaf(pr, v[vb + 1], a1);
        }
    }
    h[base + d0]     += a0;
    h[base + d0 + 1] += a1;
}

// ---------------------------------------------------------------- GLU
__global__ void glu_kernel(const float* __restrict__ cg, float* __restrict__ ca) {
    int idx = blockIdx.x * blockDim.x + threadIdx.x;   // NTOK*DMODEL
    int d = idx & (DMODEL - 1);
    int row = idx >> 9;
    float a = cg[(size_t)row * CEDIM + d];
    float gate = cg[(size_t)row * CEDIM + DMODEL + d];
    ca[idx] = a / (1.0f + expf(-gate));   // a * sigmoid(gate)
}

// ------------------------------------------------------- depthwise conv + BN + swish
__global__ void dwconv_kernel(const float* __restrict__ ca,
                              const float* __restrict__ dw_w,
                              const float* __restrict__ dw_b,
                              const float* __restrict__ bn_g,
                              const float* __restrict__ bn_b,
                              float* __restrict__ out) {
    int idx = blockIdx.x * blockDim.x + threadIdx.x;   // NTOK*DMODEL
    int d = idx & (DMODEL - 1);
    int row = idx >> 9;
    int t = row & (TSEQ - 1);
    int bstart = row - t;
    float acc = 0.0f;
    #pragma unroll
    for (int j = 0; j < KSIZE; j++) {
        int pos = t + j - 15;
        if (pos >= 0 && pos < TSEQ)
            acc = fmaf(ca[(size_t)(bstart + pos) * DMODEL + d], dw_w[j * DMODEL + d], acc);
    }
    acc += dw_b[d];
    float hx = acc * rsqrtf(1.0f + 1e-5f) * bn_g[d] + bn_b[d];
    out[idx] = swishf(hx);
}

// ---------------------------------------------------------------- launch
static inline dim3 gemm_grid(int M, int N) { return dim3(N / 128, M / 128); }

extern "C" void kernel_launch(void* const* d_in, const int* in_sizes, int n_in,
                              void* d_out, int out_size) {
    const float* x          = (const float*)d_in[0];
    const float* ff1_ln_g   = (const float*)d_in[1];
    const float* ff1_ln_b   = (const float*)d_in[2];
    const float* ff1_w1     = (const float*)d_in[3];
    const float* ff1_b1     = (const float*)d_in[4];
    const float* ff1_w2     = (const float*)d_in[5];
    const float* ff1_b2     = (const float*)d_in[6];
    const float* ff2_ln_g   = (const float*)d_in[7];
    const float* ff2_ln_b   = (const float*)d_in[8];
    const float* ff2_w1     = (const float*)d_in[9];
    const float* ff2_b1     = (const float*)d_in[10];
    const float* ff2_w2     = (const float*)d_in[11];
    const float* ff2_b2     = (const float*)d_in[12];
    const float* wq         = (const float*)d_in[13];
    const float* bq         = (const float*)d_in[14];
    const float* wk         = (const float*)d_in[15];
    const float* bk         = (const float*)d_in[16];
    const float* wv         = (const float*)d_in[17];
    const float* bv         = (const float*)d_in[18];
    const float* conv_ln_g  = (const float*)d_in[19];
    const float* conv_ln_b  = (const float*)d_in[20];
    const float* conv_pw1_w = (const float*)d_in[21];
    const float* conv_pw1_b = (const float*)d_in[22];
    const float* conv_dw_w  = (const float*)d_in[23];
    const float* conv_dw_b  = (const float*)d_in[24];
    const float* conv_bn_g  = (const float*)d_in[25];
    const float* conv_bn_b  = (const float*)d_in[26];
    const float* conv_pw2_w = (const float*)d_in[27];
    const float* conv_pw2_b = (const float*)d_in[28];
    const float* final_ln_g = (const float*)d_in[29];
    const float* final_ln_b = (const float*)d_in[30];

    float *xn, *h, *ff, *q, *k, *v, *cg, *ca, *cv, *pspill;
    cudaGetSymbolAddress((void**)&xn, g_xn);
    cudaGetSymbolAddress((void**)&h,  g_h);
    cudaGetSymbolAddress((void**)&ff, g_ff);
    cudaGetSymbolAddress((void**)&q,  g_q);
    cudaGetSymbolAddress((void**)&k,  g_k);
    cudaGetSymbolAddress((void**)&v,  g_v);
    cudaGetSymbolAddress((void**)&cg, g_cg);
    cudaGetSymbolAddress((void**)&ca, g_ca);
    cudaGetSymbolAddress((void**)&cv, g_cv);
    cudaGetSymbolAddress((void**)&pspill, g_probs_spill);

    float* out_main  = (float*)d_out;
    float* out_probs = (out_size >= OUT_ELEMS + PROB_ELEMS)
                         ? (float*)d_out + OUT_ELEMS : pspill;

    // ---- FF1: h = x + 0.5 * (swish(LN(x)@w1+b1) @ w2 + b2)
    ln_kernel<<<NTOK, 256>>>(x, ff1_ln_g, ff1_ln_b, xn);
    gemm_tf32<1><<<gemm_grid(NTOK, FFDIM), 256>>>(xn, ff1_w1, ff1_b1, nullptr, 0.f,
                                                  ff, NTOK, FFDIM, DMODEL);
    gemm_tf32<2><<<gemm_grid(NTOK, DMODEL), 256>>>(ff, ff1_w2, ff1_b2, x, 0.5f,
                                                   h, NTOK, DMODEL, FFDIM);

    // ---- attention: q/k/v = h@W + b (one fused launch) ; h += ctx ; probs out
    {
        QKVArgs args;
        args.w[0] = wq; args.w[1] = wk; args.w[2] = wv;
        args.b[0] = bq; args.b[1] = bk; args.b[2] = bv;
        args.o[0] = q;  args.o[1] = k;  args.o[2] = v;
        dim3 grid(DMODEL / 128, NTOK / 128, 3);
        gemm_tf32_qkv<<<grid, 256>>>(args, h, NTOK, DMODEL, DMODEL);
    }
    attn_kernel<<<NTOK, 256>>>(q, k, v, h, out_probs);

    // ---- conv module: h += pw2(swish(bn(dwconv(glu(pw1(LN(h)))))))
    ln_kernel<<<NTOK, 256>>>(h, conv_ln_g, conv_ln_b, xn);
    gemm_tf32<0><<<gemm_grid(NTOK, CEDIM), 256>>>(xn, conv_pw1_w, conv_pw1_b, nullptr, 0.f,
                                                  cg, NTOK, CEDIM, DMODEL);
    glu_kernel<<<(NTOK * DMODEL) / 256, 256>>>(cg, ca);
    dwconv_kernel<<<(NTOK * DMODEL) / 256, 256>>>(ca, conv_dw_w, conv_dw_b,
                                                  conv_bn_g, conv_bn_b, cv);
    gemm_tf32<2><<<gemm_grid(NTOK, DMODEL), 256>>>(cv, conv_pw2_w, conv_pw2_b, h, 1.0f,
                                                   h, NTOK, DMODEL, DMODEL);

    // ---- FF2: h = h + 0.5 * (swish(LN(h)@w1+b1) @ w2 + b2)
    ln_kernel<<<NTOK, 256>>>(h, ff2_ln_g, ff2_ln_b, xn);
    gemm_tf32<1><<<gemm_grid(NTOK, FFDIM), 256>>>(xn, ff2_w1, ff2_b1, nullptr, 0.f,
                                                  ff, NTOK, FFDIM, DMODEL);
    gemm_tf32<2><<<gemm_grid(NTOK, DMODEL), 256>>>(ff, ff2_w2, ff2_b2, h, 0.5f,
                                                   h, NTOK, DMODEL, FFDIM);

    // ---- final LN -> out
    ln_kernel<<<NTOK, 256>>>(h, final_ln_g, final_ln_b, out_main);
}

// round 5
// speedup vs baseline: 3.1673x; 1.2977x over previous
#include <cuda_runtime.h>
#include <math.h>
#include <stdint.h>

// ----------------------------------------------------------------------------
// ConformerBlock: B=4, T=1024, D=512, H=8, DH=64, W1=32, WB=65, FF=2048,
// CE=1024, KS=31.
//   h  = x + 0.5*FF1(x)
//   h += longformer_attn(h)   (also emits probs)
//   h += conv_module(h)
//   h += 0.5*FF2(h)
//   out = LN(h)
// GEMMs: tf32 mma.sync (fp32 accum), cp.async 3-stage pipeline, raw-fp32
// operands (HW tf32 truncation). Everything else fp32.
// ----------------------------------------------------------------------------

#define NTOK   4096          // B*T
#define DMODEL 512
#define TSEQ   1024
#define NHEAD  8
#define DHEAD  64
#define WB     65
#define FFDIM  2048
#define CEDIM  1024
#define KSIZE  31
#define OUT_ELEMS   (NTOK * DMODEL)          // 2097152
#define PROB_ELEMS  (NTOK * NHEAD * WB)      // 2129920

// ---- scratch (static device memory; no allocations allowed) ----
__device__ __align__(16) float g_xn[NTOK * DMODEL];
__device__ __align__(16) float g_h [NTOK * DMODEL];
__device__ __align__(16) float g_ff[NTOK * FFDIM];
__device__ __align__(16) float g_q [NTOK * DMODEL];
__device__ __align__(16) float g_k [NTOK * DMODEL];
__device__ __align__(16) float g_v [NTOK * DMODEL];
__device__ __align__(16) float g_cg[NTOK * CEDIM];
__device__ __align__(16) float g_ca[NTOK * DMODEL];
__device__ __align__(16) float g_cv[NTOK * DMODEL];
__device__ __align__(16) float g_probs_spill[PROB_ELEMS];

// ---------------------------------------------------------------- helpers
__device__ __forceinline__ float warp_sum(float v) {
    #pragma unroll
    for (int o = 16; o > 0; o >>= 1) v += __shfl_xor_sync(0xffffffffu, v, o);
    return v;
}
__device__ __forceinline__ float warp_max(float v) {
    #pragma unroll
    for (int o = 16; o > 0; o >>= 1) v = fmaxf(v, __shfl_xor_sync(0xffffffffu, v, o));
    return v;
}
__device__ __forceinline__ float swishf(float x) {
    return x / (1.0f + expf(-x));
}
__device__ __forceinline__ void mma_tf32(float c[4], const uint32_t a[4], const uint32_t b[2]) {
    asm volatile(
        "mma.sync.aligned.m16n8k8.row.col.f32.tf32.tf32.f32 "
        "{%0,%1,%2,%3}, {%4,%5,%6,%7}, {%8,%9}, {%0,%1,%2,%3};"
        : "+f"(c[0]), "+f"(c[1]), "+f"(c[2]), "+f"(c[3])
        : "r"(a[0]), "r"(a[1]), "r"(a[2]), "r"(a[3]), "r"(b[0]), "r"(b[1]));
}
__device__ __forceinline__ void cp16(uint32_t dst_smem, const void* src) {
    asm volatile("cp.async.cg.shared.global [%0], [%1], 16;"
                 :: "r"(dst_smem), "l"(src));
}
__device__ __forceinline__ void cp_commit() {
    asm volatile("cp.async.commit_group;");
}
__device__ __forceinline__ void cp_wait1() {
    asm volatile("cp.async.wait_group 1;");
}

// ---------------------------------------------------------------- tf32 GEMM
// C[M,N] = epilogue(A[M,K] @ B[K,N] + bias[N])
// MODE 0: bias only     MODE 1: swish(.)     MODE 2: res + scale*(.)
// 128x128 CTA tile, BK=16, 3-stage cp.async, 256 threads (8 warps, 4x2),
// warp tile 32x64. A swizzle: col ^ ((row&6)<<1). B swizzle: col ^ ((k&3)*8).
template <int MODE>
__device__ __forceinline__
void gemm_body(const float* __restrict__ A, const float* __restrict__ Bm,
               const float* __restrict__ bias, const float* __restrict__ res,
               float scale, float* __restrict__ C,
               int M, int N, int K, int bm, int bn) {
    __shared__ __align__(16) uint32_t As[3][128][16];   // 24 KB
    __shared__ __align__(16) uint32_t Bs[3][16][128];   // 24 KB

    int tid  = threadIdx.x;
    int lane = tid & 31, wid = tid >> 5;
    int g = lane >> 2, tg = lane & 3;
    int m0w = (wid >> 1) * 32;
    int n0w = (wid & 1) * 64;

    // cp.async chunk mapping: 2 A-chunks + 2 B-chunks of 16B per thread/stage
    int ac0_row = tid >> 2,            ac0_k = (tid & 3) * 4;          // chunks 0..255
    int ac1_row = (tid + 256) >> 2,    ac1_k = ac0_k;                  // chunks 256..511
    int bc0_row = tid >> 5,            bc0_n = (tid & 31) * 4;
    int bc1_row = (tid + 256) >> 5,    bc1_n = bc0_n;

    const float* a0src = A + (size_t)(bm + ac0_row) * K + ac0_k;
    const float* a1src = A + (size_t)(bm + ac1_row) * K + ac1_k;
    const float* b0src = Bm + (size_t)bc0_row * N + bn + bc0_n;
    const float* b1src = Bm + (size_t)bc1_row * N + bn + bc1_n;

    // swizzled smem word offsets (within a stage)
    int a0_off = ac0_row * 16 + (ac0_k ^ ((ac0_row & 6) << 1));
    int a1_off = ac1_row * 16 + (ac1_k ^ ((ac1_row & 6) << 1));
    int b0_off = bc0_row * 128 + (bc0_n ^ ((bc0_row & 3) * 8));
    int b1_off = bc1_row * 128 + (bc1_n ^ ((bc1_row & 3) * 8));

    uint32_t sA = (uint32_t)__cvta_generic_to_shared(&As[0][0][0]);
    uint32_t sB = (uint32_t)__cvta_generic_to_shared(&Bs[0][0][0]);

    float acc[2][8][4];
    #pragma unroll
    for (int mt = 0; mt < 2; mt++)
        #pragma unroll
        for (int nt = 0; nt < 8; nt++)
            #pragma unroll
            for (int i = 0; i < 4; i++) acc[mt][nt][i] = 0.0f;

    const int AST = 128 * 16 * 4;   // stage stride bytes (A)
    const int BST = 16 * 128 * 4;   // stage stride bytes (B)

    // prologue: stages 0 and 1
    cp16(sA + 0 * AST + a0_off * 4, a0src);
    cp16(sA + 0 * AST + a1_off * 4, a1src);
    cp16(sB + 0 * BST + b0_off * 4, b0src);
    cp16(sB + 0 * BST + b1_off * 4, b1src);
    cp_commit();
    cp16(sA + 1 * AST + a0_off * 4, a0src + 16);
    cp16(sA + 1 * AST + a1_off * 4, a1src + 16);
    cp16(sB + 1 * BST + b0_off * 4, b0src + (size_t)16 * N);
    cp16(sB + 1 * BST + b1_off * 4, b1src + (size_t)16 * N);
    cp_commit();

    int niter = K / 16;
    int p = 0;
    for (int it = 0; it < niter; it++) {
        cp_wait1();
        __syncthreads();

        // issue stage it+2 into buffer (it+2)%3
        int kf = (it + 2) * 16;
        if (kf < K) {
            int pf = p + 2; if (pf >= 3) pf -= 3;
            cp16(sA + pf * AST + a0_off * 4, a0src + kf);
            cp16(sA + pf * AST + a1_off * 4, a1src + kf);
            cp16(sB + pf * BST + b0_off * 4, b0src + (size_t)kf * N);
            cp16(sB + pf * BST + b1_off * 4, b1src + (size_t)kf * N);
        }
        cp_commit();

        #pragma unroll
        for (int kk = 0; kk < 16; kk += 8) {
            uint32_t af[2][4], bf[8][2];
            int asw = (kk + tg) ^ 0;   // column index before row-swizzle
            #pragma unroll
            for (int mt = 0; mt < 2; mt++) {
                int r0 = m0w + mt * 16 + g;
                int sw = (r0 & 6) << 1;
                af[mt][0] = As[p][r0][(kk + tg) ^ sw];
                af[mt][1] = As[p][r0 + 8][(kk + tg) ^ sw];
                af[mt][2] = As[p][r0][(kk + tg + 4) ^ sw];
                af[mt][3] = As[p][r0 + 8][(kk + tg + 4) ^ sw];
            }
            (void)asw;
            #pragma unroll
            for (int nt = 0; nt < 8; nt++) {
                int cs = (n0w + nt * 8 + g) ^ (tg * 8);
                bf[nt][0] = Bs[p][kk + tg][cs];
                bf[nt][1] = Bs[p][kk + tg + 4][cs];
            }
            #pragma unroll
            for (int mt = 0; mt < 2; mt++)
                #pragma unroll
                for (int nt = 0; nt < 8; nt++)
                    mma_tf32(acc[mt][nt], af[mt], bf[nt]);
        }
        p++; if (p >= 3) p = 0;
    }

    // epilogue
    #pragma unroll
    for (int mt = 0; mt < 2; mt++) {
        int row0 = bm + m0w + mt * 16 + g;
        #pragma unroll
        for (int nt = 0; nt < 8; nt++) {
            int col = bn + n0w + nt * 8 + tg * 2;
            float bb0 = bias[col], bb1 = bias[col + 1];
            float v0 = acc[mt][nt][0] + bb0;
            float v1 = acc[mt][nt][1] + bb1;
            float v2 = acc[mt][nt][2] + bb0;
            float v3 = acc[mt][nt][3] + bb1;
            if (MODE == 1) {
                v0 = swishf(v0); v1 = swishf(v1); v2 = swishf(v2); v3 = swishf(v3);
            }
            if (MODE == 2) {
                const float* r0p = res + (size_t)row0 * N + col;
                const float* r1p = res + (size_t)(row0 + 8) * N + col;
                v0 = r0p[0] + scale * v0;
                v1 = r0p[1] + scale * v1;
                v2 = r1p[0] + scale * v2;
                v3 = r1p[1] + scale * v3;
            }
            *(float2*)(C + (size_t)row0 * N + col)       = make_float2(v0, v1);
            *(float2*)(C + (size_t)(row0 + 8) * N + col) = make_float2(v2, v3);
        }
    }
}

template <int MODE>
__global__ __launch_bounds__(256, 2)
void gemm_tf32(const float* __restrict__ A, const float* __restrict__ B,
               const float* __restrict__ bias, const float* __restrict__ res,
               float scale, float* __restrict__ C, int M, int N, int K) {
    gemm_body<MODE>(A, B, bias, res, scale, C, M, N, K,
                    blockIdx.y * 128, blockIdx.x * 128);
}

struct QKVArgs {
    const float* w[3];
    const float* b[3];
    float* o[3];
};

__global__ __launch_bounds__(256, 2)
void gemm_tf32_qkv(QKVArgs args, const float* __restrict__ A, int M, int N, int K) {
    int z = blockIdx.z;
    gemm_body<0>(A, args.w[z], args.b[z], nullptr, 0.0f, args.o[z],
                 M, N, K, blockIdx.y * 128, blockIdx.x * 128);
}

// ---------------------------------------------------------------- LayerNorm
__global__ void ln_kernel(const float* __restrict__ x,
                          const float* __restrict__ g,
                          const float* __restrict__ b,
                          float* __restrict__ out) {
    int row = blockIdx.x;
    int tid = threadIdx.x;
    const float* xr = x + (size_t)row * DMODEL;
    float v0 = xr[tid], v1 = xr[tid + 256];
    float s = v0 + v1;
    float q = v0 * v0 + v1 * v1;
    s = warp_sum(s);
    q = warp_sum(q);
    __shared__ float sh[16];
    int w = tid >> 5, l = tid & 31;
    if (l == 0) { sh[w] = s; sh[w + 8] = q; }
    __syncthreads();
    if (w == 0) {
        float a = (l < 8) ? sh[l] : 0.0f;
        float c = (l < 8) ? sh[l + 8] : 0.0f;
        a = warp_sum(a);
        c = warp_sum(c);
        if (l == 0) { sh[0] = a; sh[1] = c; }
    }
    __syncthreads();
    float mean = sh[0] * (1.0f / DMODEL);
    float var  = sh[1] * (1.0f / DMODEL) - mean * mean;
    float inv  = rsqrtf(var + 1e-5f);
    float* orow = out + (size_t)row * DMODEL;
    orow[tid]       = (v0 - mean) * inv * g[tid]       + b[tid];
    orow[tid + 256] = (v1 - mean) * inv * g[tid + 256] + b[tid + 256];
}

// ---------------------------------------------------------------- attention
__global__ __launch_bounds__(256)
void attn_kernel(const float* __restrict__ q, const float* __restrict__ k,
                 const float* __restrict__ v, float* __restrict__ h,
                 float* __restrict__ probs) {
    int row = blockIdx.x;             // 0..4095
    int t = row & (TSEQ - 1);
    int bstart = row - t;             // b*T
    int head = threadIdx.x >> 5;
    int lane = threadIdx.x & 31;
    int d0 = lane * 2;
    int base = row * DMODEL + head * DHEAD;

    float q0 = q[base + d0] * 0.125f;
    float q1 = q[base + d0 + 1] * 0.125f;

    __shared__ float sc[NHEAD][WB + 3];
    float* scrow = sc[head];

    for (int w = 0; w < WB; w++) {
        int pos = t + w - 32;
        float s = -1e9f;
        if (pos >= 0 && pos < TSEQ) {
            int kb = (bstart + pos) * DMODEL + head * DHEAD + d0;
            float p = q0 * k[kb] + q1 * k[kb + 1];
            p = warp_sum(p);
            s = p;
        }
        if (lane == 0) scrow[w] = s;
    }
    __syncwarp();

    float m = -1e9f;
    for (int w = lane; w < WB; w += 32) m = fmaxf(m, scrow[w]);
    m = warp_max(m);

    float sum = 0.0f;
    for (int w = lane; w < WB; w += 32) {
        float e = expf(scrow[w] - m);
        scrow[w] = e;
        sum += e;
    }
    sum = warp_sum(sum);
    float inv = 1.0f / sum;

    float* prow = probs + ((size_t)row * NHEAD + head) * WB;
    for (int w = lane; w < WB; w += 32) {
        float pr = scrow[w] * inv;
        scrow[w] = pr;
        prow[w] = pr;
    }
    __syncwarp();

    float a0 = 0.0f, a1 = 0.0f;
    for (int w = 0; w < WB; w++) {
        int pos = t + w - 32;
        if (pos >= 0 && pos < TSEQ) {
            float pr = scrow[w];
            int vb = (bstart + pos) * DMODEL + head * DHEAD + d0;
            a0 = fmaf(pr, v[vb], a0);
            a1 = fmaf(pr, v[vb + 1], a1);
        }
    }
    h[base + d0]     += a0;
    h[base + d0 + 1] += a1;
}

// ---------------------------------------------------------------- GLU
__global__ void glu_kernel(const float* __restrict__ cg, float* __restrict__ ca) {
    int idx = blockIdx.x * blockDim.x + threadIdx.x;   // NTOK*DMODEL
    int d = idx & (DMODEL - 1);
    int row = idx >> 9;
    float a = cg[(size_t)row * CEDIM + d];
    float gate = cg[(size_t)row * CEDIM + DMODEL + d];
    ca[idx] = a / (1.0f + expf(-gate));   // a * sigmoid(gate)
}

// ------------------------------------------------------- depthwise conv + BN + swish
__global__ void dwconv_kernel(const float* __restrict__ ca,
                              const float* __restrict__ dw_w,
                              const float* __restrict__ dw_b,
                              const float* __restrict__ bn_g,
                              const float* __restrict__ bn_b,
                              float* __restrict__ out) {
    int idx = blockIdx.x * blockDim.x + threadIdx.x;   // NTOK*DMODEL
    int d = idx & (DMODEL - 1);
    int row = idx >> 9;
    int t = row & (TSEQ - 1);
    int bstart = row - t;
    float acc = 0.0f;
    #pragma unroll
    for (int j = 0; j < KSIZE; j++) {
        int pos = t + j - 15;
        if (pos >= 0 && pos < TSEQ)
            acc = fmaf(ca[(size_t)(bstart + pos) * DMODEL + d], dw_w[j * DMODEL + d], acc);
    }
    acc += dw_b[d];
    float hx = acc * rsqrtf(1.0f + 1e-5f) * bn_g[d] + bn_b[d];
    out[idx] = swishf(hx);
}

// ---------------------------------------------------------------- launch
static inline dim3 gemm_grid(int M, int N) { return dim3(N / 128, M / 128); }

extern "C" void kernel_launch(void* const* d_in, const int* in_sizes, int n_in,
                              void* d_out, int out_size) {
    const float* x          = (const float*)d_in[0];
    const float* ff1_ln_g   = (const float*)d_in[1];
    const float* ff1_ln_b   = (const float*)d_in[2];
    const float* ff1_w1     = (const float*)d_in[3];
    const float* ff1_b1     = (const float*)d_in[4];
    const float* ff1_w2     = (const float*)d_in[5];
    const float* ff1_b2     = (const float*)d_in[6];
    const float* ff2_ln_g   = (const float*)d_in[7];
    const float* ff2_ln_b   = (const float*)d_in[8];
    const float* ff2_w1     = (const float*)d_in[9];
    const float* ff2_b1     = (const float*)d_in[10];
    const float* ff2_w2     = (const float*)d_in[11];
    const float* ff2_b2     = (const float*)d_in[12];
    const float* wq         = (const float*)d_in[13];
    const float* bq         = (const float*)d_in[14];
    const float* wk         = (const float*)d_in[15];
    const float* bk         = (const float*)d_in[16];
    const float* wv         = (const float*)d_in[17];
    const float* bv         = (const float*)d_in[18];
    const float* conv_ln_g  = (const float*)d_in[19];
    const float* conv_ln_b  = (const float*)d_in[20];
    const float* conv_pw1_w = (const float*)d_in[21];
    const float* conv_pw1_b = (const float*)d_in[22];
    const float* conv_dw_w  = (const float*)d_in[23];
    const float* conv_dw_b  = (const float*)d_in[24];
    const float* conv_bn_g  = (const float*)d_in[25];
    const float* conv_bn_b  = (const float*)d_in[26];
    const float* conv_pw2_w = (const float*)d_in[27];
    const float* conv_pw2_b = (const float*)d_in[28];
    const float* final_ln_g = (const float*)d_in[29];
    const float* final_ln_b = (const float*)d_in[30];

    float *xn, *h, *ff, *q, *k, *v, *cg, *ca, *cv, *pspill;
    cudaGetSymbolAddress((void**)&xn, g_xn);
    cudaGetSymbolAddress((void**)&h,  g_h);
    cudaGetSymbolAddress((void**)&ff, g_ff);
    cudaGetSymbolAddress((void**)&q,  g_q);
    cudaGetSymbolAddress((void**)&k,  g_k);
    cudaGetSymbolAddress((void**)&v,  g_v);
    cudaGetSymbolAddress((void**)&cg, g_cg);
    cudaGetSymbolAddress((void**)&ca, g_ca);
    cudaGetSymbolAddress((void**)&cv, g_cv);
    cudaGetSymbolAddress((void**)&pspill, g_probs_spill);

    float* out_main  = (float*)d_out;
    float* out_probs = (out_size >= OUT_ELEMS + PROB_ELEMS)
                         ? (float*)d_out + OUT_ELEMS : pspill;

    // ---- FF1: h = x + 0.5 * (swish(LN(x)@w1+b1) @ w2 + b2)
    ln_kernel<<<NTOK, 256>>>(x, ff1_ln_g, ff1_ln_b, xn);
    gemm_tf32<1><<<gemm_grid(NTOK, FFDIM), 256>>>(xn, ff1_w1, ff1_b1, nullptr, 0.f,
                                                  ff, NTOK, FFDIM, DMODEL);
    gemm_tf32<2><<<gemm_grid(NTOK, DMODEL), 256>>>(ff, ff1_w2, ff1_b2, x, 0.5f,
                                                   h, NTOK, DMODEL, FFDIM);

    // ---- attention: q/k/v = h@W + b (one fused launch) ; h += ctx ; probs out
    {
        QKVArgs args;
        args.w[0] = wq; args.w[1] = wk; args.w[2] = wv;
        args.b[0] = bq; args.b[1] = bk; args.b[2] = bv;
        args.o[0] = q;  args.o[1] = k;  args.o[2] = v;
        dim3 grid(DMODEL / 128, NTOK / 128, 3);
        gemm_tf32_qkv<<<grid, 256>>>(args, h, NTOK, DMODEL, DMODEL);
    }
    attn_kernel<<<NTOK, 256>>>(q, k, v, h, out_probs);

    // ---- conv module: h += pw2(swish(bn(dwconv(glu(pw1(LN(h)))))))
    ln_kernel<<<NTOK, 256>>>(h, conv_ln_g, conv_ln_b, xn);
    gemm_tf32<0><<<gemm_grid(NTOK, CEDIM), 256>>>(xn, conv_pw1_w, conv_pw1_b, nullptr, 0.f,
                                                  cg, NTOK, CEDIM, DMODEL);
    glu_kernel<<<(NTOK * DMODEL) / 256, 256>>>(cg, ca);
    dwconv_kernel<<<(NTOK * DMODEL) / 256, 256>>>(ca, conv_dw_w, conv_dw_b,
                                                  conv_bn_g, conv_bn_b, cv);
    gemm_tf32<2><<<gemm_grid(NTOK, DMODEL), 256>>>(cv, conv_pw2_w, conv_pw2_b, h, 1.0f,
                                                   h, NTOK, DMODEL, DMODEL);

    // ---- FF2: h = h + 0.5 * (swish(LN(h)@w1+b1) @ w2 + b2)
    ln_kernel<<<NTOK, 256>>>(h, ff2_ln_g, ff2_ln_b, xn);
    gemm_tf32<1><<<gemm_grid(NTOK, FFDIM), 256>>>(xn, ff2_w1, ff2_b1, nullptr, 0.f,
                                                  ff, NTOK, FFDIM, DMODEL);
    gemm_tf32<2><<<gemm_grid(NTOK, DMODEL), 256>>>(ff, ff2_w2, ff2_b2, h, 0.5f,
                                                   h, NTOK, DMODEL, FFDIM);

    // ---- final LN -> out
    ln_kernel<<<NTOK, 256>>>(h, final_ln_g, final_ln_b, out_main);
}

// round 6
// speedup vs baseline: 3.5392x; 1.1174x over previous
#include <cuda_runtime.h>
#include <math.h>
#include <stdint.h>

// ----------------------------------------------------------------------------
// ConformerBlock: B=4, T=1024, D=512, H=8, DH=64, W1=32, WB=65, FF=2048,
// CE=1024, KS=31.
//   h  = x + 0.5*FF1(x)
//   h += longformer_attn(h)   (also emits probs)
//   h += conv_module(h)
//   h += 0.5*FF2(h)
//   out = LN(h)
// GEMMs: tf32 mma.sync + cp.async 3-stage. Attention: butterfly reduce-scatter.
// Conv: fused GLU+depthwise with smem tiling.
// ----------------------------------------------------------------------------

#define NTOK   4096          // B*T
#define DMODEL 512
#define TSEQ   1024
#define NHEAD  8
#define DHEAD  64
#define WB     65
#define FFDIM  2048
#define CEDIM  1024
#define KSIZE  31
#define OUT_ELEMS   (NTOK * DMODEL)          // 2097152
#define PROB_ELEMS  (NTOK * NHEAD * WB)      // 2129920

// ---- scratch (static device memory; no allocations allowed) ----
__device__ __align__(16) float g_xn[NTOK * DMODEL];
__device__ __align__(16) float g_h [NTOK * DMODEL];
__device__ __align__(16) float g_ff[NTOK * FFDIM];
__device__ __align__(16) float g_q [NTOK * DMODEL];
__device__ __align__(16) float g_k [NTOK * DMODEL];
__device__ __align__(16) float g_v [NTOK * DMODEL];
__device__ __align__(16) float g_cg[NTOK * CEDIM];
__device__ __align__(16) float g_cv[NTOK * DMODEL];
__device__ __align__(16) float g_probs_spill[PROB_ELEMS];

// ---------------------------------------------------------------- helpers
__device__ __forceinline__ float warp_sum(float v) {
    #pragma unroll
    for (int o = 16; o > 0; o >>= 1) v += __shfl_xor_sync(0xffffffffu, v, o);
    return v;
}
__device__ __forceinline__ float warp_max(float v) {
    #pragma unroll
    for (int o = 16; o > 0; o >>= 1) v = fmaxf(v, __shfl_xor_sync(0xffffffffu, v, o));
    return v;
}
__device__ __forceinline__ float swishf(float x) {
    return x / (1.0f + expf(-x));
}
__device__ __forceinline__ void mma_tf32(float c[4], const uint32_t a[4], const uint32_t b[2]) {
    asm volatile(
        "mma.sync.aligned.m16n8k8.row.col.f32.tf32.tf32.f32 "
        "{%0,%1,%2,%3}, {%4,%5,%6,%7}, {%8,%9}, {%0,%1,%2,%3};"
        : "+f"(c[0]), "+f"(c[1]), "+f"(c[2]), "+f"(c[3])
        : "r"(a[0]), "r"(a[1]), "r"(a[2]), "r"(a[3]), "r"(b[0]), "r"(b[1]));
}
__device__ __forceinline__ void cp16(uint32_t dst_smem, const void* src) {
    asm volatile("cp.async.cg.shared.global [%0], [%1], 16;"
                 :: "r"(dst_smem), "l"(src));
}
__device__ __forceinline__ void cp_commit() {
    asm volatile("cp.async.commit_group;");
}
__device__ __forceinline__ void cp_wait1() {
    asm volatile("cp.async.wait_group 1;");
}

// ---------------------------------------------------------------- tf32 GEMM
// C[M,N] = epilogue(A[M,K] @ B[K,N] + bias[N])
// MODE 0: bias only     MODE 1: swish(.)     MODE 2: res + scale*(.)
template <int MODE>
__device__ __forceinline__
void gemm_body(const float* __restrict__ A, const float* __restrict__ Bm,
               const float* __restrict__ bias, const float* __restrict__ res,
               float scale, float* __restrict__ C,
               int M, int N, int K, int bm, int bn) {
    __shared__ __align__(16) uint32_t As[3][128][16];   // 24 KB
    __shared__ __align__(16) uint32_t Bs[3][16][128];   // 24 KB

    int tid  = threadIdx.x;
    int lane = tid & 31, wid = tid >> 5;
    int g = lane >> 2, tg = lane & 3;
    int m0w = (wid >> 1) * 32;
    int n0w = (wid & 1) * 64;

    int ac0_row = tid >> 2,            ac0_k = (tid & 3) * 4;
    int ac1_row = (tid + 256) >> 2,    ac1_k = ac0_k;
    int bc0_row = tid >> 5,            bc0_n = (tid & 31) * 4;
    int bc1_row = (tid + 256) >> 5,    bc1_n = bc0_n;

    const float* a0src = A + (size_t)(bm + ac0_row) * K + ac0_k;
    const float* a1src = A + (size_t)(bm + ac1_row) * K + ac1_k;
    const float* b0src = Bm + (size_t)bc0_row * N + bn + bc0_n;
    const float* b1src = Bm + (size_t)bc1_row * N + bn + bc1_n;

    int a0_off = ac0_row * 16 + (ac0_k ^ ((ac0_row & 6) << 1));
    int a1_off = ac1_row * 16 + (ac1_k ^ ((ac1_row & 6) << 1));
    int b0_off = bc0_row * 128 + (bc0_n ^ ((bc0_row & 3) * 8));
    int b1_off = bc1_row * 128 + (bc1_n ^ ((bc1_row & 3) * 8));

    uint32_t sA = (uint32_t)__cvta_generic_to_shared(&As[0][0][0]);
    uint32_t sB = (uint32_t)__cvta_generic_to_shared(&Bs[0][0][0]);

    float acc[2][8][4];
    #pragma unroll
    for (int mt = 0; mt < 2; mt++)
        #pragma unroll
        for (int nt = 0; nt < 8; nt++)
            #pragma unroll
            for (int i = 0; i < 4; i++) acc[mt][nt][i] = 0.0f;

    const int AST = 128 * 16 * 4;
    const int BST = 16 * 128 * 4;

    cp16(sA + 0 * AST + a0_off * 4, a0src);
    cp16(sA + 0 * AST + a1_off * 4, a1src);
    cp16(sB + 0 * BST + b0_off * 4, b0src);
    cp16(sB + 0 * BST + b1_off * 4, b1src);
    cp_commit();
    cp16(sA + 1 * AST + a0_off * 4, a0src + 16);
    cp16(sA + 1 * AST + a1_off * 4, a1src + 16);
    cp16(sB + 1 * BST + b0_off * 4, b0src + (size_t)16 * N);
    cp16(sB + 1 * BST + b1_off * 4, b1src + (size_t)16 * N);
    cp_commit();

    int niter = K / 16;
    int p = 0;
    for (int it = 0; it < niter; it++) {
        cp_wait1();
        __syncthreads();

        int kf = (it + 2) * 16;
        if (kf < K) {
            int pf = p + 2; if (pf >= 3) pf -= 3;
            cp16(sA + pf * AST + a0_off * 4, a0src + kf);
            cp16(sA + pf * AST + a1_off * 4, a1src + kf);
            cp16(sB + pf * BST + b0_off * 4, b0src + (size_t)kf * N);
            cp16(sB + pf * BST + b1_off * 4, b1src + (size_t)kf * N);
        }
        cp_commit();

        #pragma unroll
        for (int kk = 0; kk < 16; kk += 8) {
            uint32_t af[2][4], bf[8][2];
            #pragma unroll
            for (int mt = 0; mt < 2; mt++) {
                int r0 = m0w + mt * 16 + g;
                int sw = (r0 & 6) << 1;
                af[mt][0] = As[p][r0][(kk + tg) ^ sw];
                af[mt][1] = As[p][r0 + 8][(kk + tg) ^ sw];
                af[mt][2] = As[p][r0][(kk + tg + 4) ^ sw];
                af[mt][3] = As[p][r0 + 8][(kk + tg + 4) ^ sw];
            }
            #pragma unroll
            for (int nt = 0; nt < 8; nt++) {
                int cs = (n0w + nt * 8 + g) ^ (tg * 8);
                bf[nt][0] = Bs[p][kk + tg][cs];
                bf[nt][1] = Bs[p][kk + tg + 4][cs];
            }
            #pragma unroll
            for (int mt = 0; mt < 2; mt++)
                #pragma unroll
                for (int nt = 0; nt < 8; nt++)
                    mma_tf32(acc[mt][nt], af[mt], bf[nt]);
        }
        p++; if (p >= 3) p = 0;
    }

    #pragma unroll
    for (int mt = 0; mt < 2; mt++) {
        int row0 = bm + m0w + mt * 16 + g;
        #pragma unroll
        for (int nt = 0; nt < 8; nt++) {
            int col = bn + n0w + nt * 8 + tg * 2;
            float bb0 = bias[col], bb1 = bias[col + 1];
            float v0 = acc[mt][nt][0] + bb0;
            float v1 = acc[mt][nt][1] + bb1;
            float v2 = acc[mt][nt][2] + bb0;
            float v3 = acc[mt][nt][3] + bb1;
            if (MODE == 1) {
                v0 = swishf(v0); v1 = swishf(v1); v2 = swishf(v2); v3 = swishf(v3);
            }
            if (MODE == 2) {
                const float* r0p = res + (size_t)row0 * N + col;
                const float* r1p = res + (size_t)(row0 + 8) * N + col;
                v0 = r0p[0] + scale * v0;
                v1 = r0p[1] + scale * v1;
                v2 = r1p[0] + scale * v2;
                v3 = r1p[1] + scale * v3;
            }
            *(float2*)(C + (size_t)row0 * N + col)       = make_float2(v0, v1);
            *(float2*)(C + (size_t)(row0 + 8) * N + col) = make_float2(v2, v3);
        }
    }
}

template <int MODE>
__global__ __launch_bounds__(256, 2)
void gemm_tf32(const float* __restrict__ A, const float* __restrict__ B,
               const float* __restrict__ bias, const float* __restrict__ res,
               float scale, float* __restrict__ C, int M, int N, int K) {
    gemm_body<MODE>(A, B, bias, res, scale, C, M, N, K,
                    blockIdx.y * 128, blockIdx.x * 128);
}

struct QKVArgs {
    const float* w[3];
    const float* b[3];
    float* o[3];
};

__global__ __launch_bounds__(256, 2)
void gemm_tf32_qkv(QKVArgs args, const float* __restrict__ A, int M, int N, int K) {
    int z = blockIdx.z;
    gemm_body<0>(A, args.w[z], args.b[z], nullptr, 0.0f, args.o[z],
                 M, N, K, blockIdx.y * 128, blockIdx.x * 128);
}

// ---------------------------------------------------------------- LayerNorm
__global__ void ln_kernel(const float* __restrict__ x,
                          const float* __restrict__ g,
                          const float* __restrict__ b,
                          float* __restrict__ out) {
    int row = blockIdx.x;
    int tid = threadIdx.x;
    const float* xr = x + (size_t)row * DMODEL;
    float v0 = xr[tid], v1 = xr[tid + 256];
    float s = v0 + v1;
    float q = v0 * v0 + v1 * v1;
    s = warp_sum(s);
    q = warp_sum(q);
    __shared__ float sh[16];
    int w = tid >> 5, l = tid & 31;
    if (l == 0) { sh[w] = s; sh[w + 8] = q; }
    __syncthreads();
    if (w == 0) {
        float a = (l < 8) ? sh[l] : 0.0f;
        float c = (l < 8) ? sh[l + 8] : 0.0f;
        a = warp_sum(a);
        c = warp_sum(c);
        if (l == 0) { sh[0] = a; sh[1] = c; }
    }
    __syncthreads();
    float mean = sh[0] * (1.0f / DMODEL);
    float var  = sh[1] * (1.0f / DMODEL) - mean * mean;
    float inv  = rsqrtf(var + 1e-5f);
    float* orow = out + (size_t)row * DMODEL;
    orow[tid]       = (v0 - mean) * inv * g[tid]       + b[tid];
    orow[tid + 256] = (v1 - mean) * inv * g[tid + 256] + b[tid + 256];
}

// ---------------------------------------------------------------- attention
// block = token, warp = head. Scores via butterfly reduce-scatter:
// each lane accumulates partials for all 32 positions of a group, then a
// 5-round butterfly leaves lane l with the full score of position l.
__global__ __launch_bounds__(256)
void attn_kernel(const float* __restrict__ q, const float* __restrict__ k,
                 const float* __restrict__ v, float* __restrict__ h,
                 float* __restrict__ probs) {
    int row = blockIdx.x;             // 0..4095
    int t = row & (TSEQ - 1);
    int bstart = row - t;             // b*T
    int head = threadIdx.x >> 5;
    int lane = threadIdx.x & 31;
    int d0 = lane * 2;
    int base = row * DMODEL + head * DHEAD;

    float q0 = q[base + d0] * 0.125f;
    float q1 = q[base + d0 + 1] * 0.125f;

    __shared__ float sc[NHEAD][WB + 3];
    float* scrow = sc[head];

    float sgrp[2];
    #pragma unroll
    for (int gsel = 0; gsel < 2; gsel++) {
        int wbase = gsel * 32;
        float acc[32];
        #pragma unroll
        for (int w = 0; w < 32; w++) {
            int pos = t + wbase + w - 32;
            float k0 = 0.0f, k1 = 0.0f;
            if (pos >= 0 && pos < TSEQ) {
                float2 kv = *(const float2*)&k[(size_t)(bstart + pos) * DMODEL + head * DHEAD + d0];
                k0 = kv.x; k1 = kv.y;
            }
            acc[w] = q0 * k0 + q1 * k1;
        }
        // butterfly reduce-scatter: lane l ends with full sum for position wbase+l
        int n = 32;
        #pragma unroll
        for (int off = 16; off >= 1; off >>= 1) {
            bool upper = (lane & off) != 0;
            #pragma unroll
            for (int j = 0; j < 16; j++) {
                if (j < n / 2) {
                    float send = upper ? acc[j] : acc[j + n / 2];
                    float recv = __shfl_xor_sync(0xffffffffu, send, off);
                    acc[j] = (upper ? acc[j + n / 2] : acc[j]) + recv;
                }
            }
            n >>= 1;
        }
        int posW = t + wbase + lane - 32;
        sgrp[gsel] = (posW >= 0 && posW < TSEQ) ? acc[0] : -1e9f;
    }

    // position 64 (pos = t+32, always >= 0)
    float s64;
    {
        int pos = t + 32;
        float p = 0.0f;
        if (pos < TSEQ) {
            float2 kv = *(const float2*)&k[(size_t)(bstart + pos) * DMODEL + head * DHEAD + d0];
            p = q0 * kv.x + q1 * kv.y;
        }
        p = warp_sum(p);
        s64 = (pos < TSEQ) ? p : -1e9f;
    }

    float m = fmaxf(fmaxf(sgrp[0], sgrp[1]), s64);
    m = warp_max(m);
    float e0 = expf(sgrp[0] - m);
    float e1 = expf(sgrp[1] - m);
    float e64 = expf(s64 - m);
    float sum = warp_sum(e0 + e1) + e64;
    float inv = 1.0f / sum;
    float p0 = e0 * inv, p1 = e1 * inv, p64 = e64 * inv;

    float* prow = probs + ((size_t)row * NHEAD + head) * WB;
    scrow[lane] = p0;
    scrow[lane + 32] = p1;
    prow[lane] = p0;
    prow[lane + 32] = p1;
    if (lane == 0) { scrow[64] = p64; prow[64] = p64; }
    __syncwarp();

    float a0 = 0.0f, a1 = 0.0f;
    for (int w = 0; w < WB; w++) {
        int pos = t + w - 32;
        if (pos >= 0 && pos < TSEQ) {
            float pr = scrow[w];
            float2 vv = *(const float2*)&v[(size_t)(bstart + pos) * DMODEL + head * DHEAD + d0];
            a0 = fmaf(pr, vv.x, a0);
            a1 = fmaf(pr, vv.y, a1);
        }
    }
    h[base + d0]     += a0;
    h[base + d0 + 1] += a1;
}

// ---------------------------------------- fused GLU + depthwise conv + BN + swish
// block = 64 tokens x 128 channels. GLU applied during smem staging of cg.
#define DW_TOK 64
#define DW_CH  128
__global__ __launch_bounds__(256)
void glu_dwconv_kernel(const float* __restrict__ cg,
                       const float* __restrict__ dw_w,
                       const float* __restrict__ dw_b,
                       const float* __restrict__ bn_g,
                       const float* __restrict__ bn_b,
                       float* __restrict__ out) {
    __shared__ float s[DW_TOK + KSIZE - 1][DW_CH];   // 94 x 128 = 47 KB
    int ct = blockIdx.x * DW_CH;
    int tt = blockIdx.y * DW_TOK;          // global token start (tile within batch)
    int t0 = tt & (TSEQ - 1);
    int bstart = tt - t0;
    int tid = threadIdx.x;

    // stage GLU(cg) for rows [t0-15, t0+78]
    for (int i = tid; i < (DW_TOK + KSIZE - 1) * DW_CH; i += 256) {
        int r = i >> 7;            // /128
        int c = i & (DW_CH - 1);
        int pos = t0 + r - 15;
        float val = 0.0f;
        if (pos >= 0 && pos < TSEQ) {
            const float* cgrow = cg + (size_t)(bstart + pos) * CEDIM;
            float a = cgrow[ct + c];
            float gate = cgrow[DMODEL + ct + c];
            val = a / (1.0f + expf(-gate));
        }
        s[r][c] = val;
    }
    __syncthreads();

    int c = tid & (DW_CH - 1);
    int trow = tid >> 7;           // 0 or 1
    // hoist per-channel weights and BN params
    float wreg[KSIZE];
    #pragma unroll
    for (int j = 0; j < KSIZE; j++) wreg[j] = dw_w[j * DMODEL + ct + c];
    float bb = dw_b[ct + c];
    float bg = bn_g[ct + c] * rsqrtf(1.0f + 1e-5f);
    float bbn = bn_b[ct + c];

    #pragma unroll 4
    for (int i = 0; i < DW_TOK / 2; i++) {
        int lt = trow + 2 * i;
        float acc = 0.0f;
        #pragma unroll
        for (int j = 0; j < KSIZE; j++)
            acc = fmaf(s[lt + j][c], wreg[j], acc);
        acc += bb;
        float hx = acc * bg + bbn;
        out[(size_t)(tt + lt) * DMODEL + ct + c] = swishf(hx);
    }
}

// ---------------------------------------------------------------- launch
static inline dim3 gemm_grid(int M, int N) { return dim3(N / 128, M / 128); }

extern "C" void kernel_launch(void* const* d_in, const int* in_sizes, int n_in,
                              void* d_out, int out_size) {
    const float* x          = (const float*)d_in[0];
    const float* ff1_ln_g   = (const float*)d_in[1];
    const float* ff1_ln_b   = (const float*)d_in[2];
    const float* ff1_w1     = (const float*)d_in[3];
    const float* ff1_b1     = (const float*)d_in[4];
    const float* ff1_w2     = (const float*)d_in[5];
    const float* ff1_b2     = (const float*)d_in[6];
    const float* ff2_ln_g   = (const float*)d_in[7];
    const float* ff2_ln_b   = (const float*)d_in[8];
    const float* ff2_w1     = (const float*)d_in[9];
    const float* ff2_b1     = (const float*)d_in[10];
    const float* ff2_w2     = (const float*)d_in[11];
    const float* ff2_b2     = (const float*)d_in[12];
    const float* wq         = (const float*)d_in[13];
    const float* bq         = (const float*)d_in[14];
    const float* wk         = (const float*)d_in[15];
    const float* bk         = (const float*)d_in[16];
    const float* wv         = (const float*)d_in[17];
    const float* bv         = (const float*)d_in[18];
    const float* conv_ln_g  = (const float*)d_in[19];
    const float* conv_ln_b  = (const float*)d_in[20];
    const float* conv_pw1_w = (const float*)d_in[21];
    const float* conv_pw1_b = (const float*)d_in[22];
    const float* conv_dw_w  = (const float*)d_in[23];
    const float* conv_dw_b  = (const float*)d_in[24];
    const float* conv_bn_g  = (const float*)d_in[25];
    const float* conv_bn_b  = (const float*)d_in[26];
    const float* conv_pw2_w = (const float*)d_in[27];
    const float* conv_pw2_b = (const float*)d_in[28];
    const float* final_ln_g = (const float*)d_in[29];
    const float* final_ln_b = (const float*)d_in[30];

    float *xn, *h, *ff, *q, *k, *v, *cg, *cv, *pspill;
    cudaGetSymbolAddress((void**)&xn, g_xn);
    cudaGetSymbolAddress((void**)&h,  g_h);
    cudaGetSymbolAddress((void**)&ff, g_ff);
    cudaGetSymbolAddress((void**)&q,  g_q);
    cudaGetSymbolAddress((void**)&k,  g_k);
    cudaGetSymbolAddress((void**)&v,  g_v);
    cudaGetSymbolAddress((void**)&cg, g_cg);
    cudaGetSymbolAddress((void**)&cv, g_cv);
    cudaGetSymbolAddress((void**)&pspill, g_probs_spill);

    float* out_main  = (float*)d_out;
    float* out_probs = (out_size >= OUT_ELEMS + PROB_ELEMS)
                         ? (float*)d_out + OUT_ELEMS : pspill;

    // ---- FF1: h = x + 0.5 * (swish(LN(x)@w1+b1) @ w2 + b2)
    ln_kernel<<<NTOK, 256>>>(x, ff1_ln_g, ff1_ln_b, xn);
    gemm_tf32<1><<<gemm_grid(NTOK, FFDIM), 256>>>(xn, ff1_w1, ff1_b1, nullptr, 0.f,
                                                  ff, NTOK, FFDIM, DMODEL);
    gemm_tf32<2><<<gemm_grid(NTOK, DMODEL), 256>>>(ff, ff1_w2, ff1_b2, x, 0.5f,
                                                   h, NTOK, DMODEL, FFDIM);

    // ---- attention
    {
        QKVArgs args;
        args.w[0] = wq; args.w[1] = wk; args.w[2] = wv;
        args.b[0] = bq; args.b[1] = bk; args.b[2] = bv;
        args.o[0] = q;  args.o[1] = k;  args.o[2] = v;
        dim3 grid(DMODEL / 128, NTOK / 128, 3);
        gemm_tf32_qkv<<<grid, 256>>>(args, h, NTOK, DMODEL, DMODEL);
    }
    attn_kernel<<<NTOK, 256>>>(q, k, v, h, out_probs);

    // ---- conv module
    ln_kernel<<<NTOK, 256>>>(h, conv_ln_g, conv_ln_b, xn);
    gemm_tf32<0><<<gemm_grid(NTOK, CEDIM), 256>>>(xn, conv_pw1_w, conv_pw1_b, nullptr, 0.f,
                                                  cg, NTOK, CEDIM, DMODEL);
    {
        dim3 grid(DMODEL / DW_CH, NTOK / DW_TOK);
        glu_dwconv_kernel<<<grid, 256>>>(cg, conv_dw_w, conv_dw_b,
                                         conv_bn_g, conv_bn_b, cv);
    }
    gemm_tf32<2><<<gemm_grid(NTOK, DMODEL), 256>>>(cv, conv_pw2_w, conv_pw2_b, h, 1.0f,
                                                   h, NTOK, DMODEL, DMODEL);

    // ---- FF2
    ln_kernel<<<NTOK, 256>>>(h, ff2_ln_g, ff2_ln_b, xn);
    gemm_tf32<1><<<gemm_grid(NTOK, FFDIM), 256>>>(xn, ff2_w1, ff2_b1, nullptr, 0.f,
                                                  ff, NTOK, FFDIM, DMODEL);
    gemm_tf32<2><<<gemm_grid(NTOK, DMODEL), 256>>>(ff, ff2_w2, ff2_b2, h, 0.5f,
                                                   h, NTOK, DMODEL, FFDIM);

    // ---- final LN -> out
    ln_kernel<<<NTOK, 256>>>(h, final_ln_g, final_ln_b, out_main);
}

// round 7
// speedup vs baseline: 3.7156x; 1.0498x over previous
#include <cuda_runtime.h>
#include <math.h>
#include <stdint.h>

// ----------------------------------------------------------------------------
// ConformerBlock: B=4, T=1024, D=512, H=8, DH=64, W1=32, WB=65, FF=2048,
// CE=1024, KS=31.
//   h  = x + 0.5*FF1(x)
//   h += longformer_attn(h)   (also emits probs)
//   h += conv_module(h)
//   h += 0.5*FF2(h)
//   out = LN(h)
// GEMMs: tf32 mma.sync + cp.async 3-stage + ldmatrix fragment loads
// (weights pre-transposed to n-major). Attention: butterfly reduce-scatter.
// Conv: fused GLU+depthwise with smem tiling.
// ----------------------------------------------------------------------------

#define NTOK   4096          // B*T
#define DMODEL 512
#define TSEQ   1024
#define NHEAD  8
#define DHEAD  64
#define WB     65
#define FFDIM  2048
#define CEDIM  1024
#define KSIZE  31
#define OUT_ELEMS   (NTOK * DMODEL)          // 2097152
#define PROB_ELEMS  (NTOK * NHEAD * WB)      // 2129920

// ---- scratch (static device memory; no allocations allowed) ----
__device__ __align__(16) float g_xn[NTOK * DMODEL];
__device__ __align__(16) float g_h [NTOK * DMODEL];
__device__ __align__(16) float g_ff[NTOK * FFDIM];
__device__ __align__(16) float g_q [NTOK * DMODEL];
__device__ __align__(16) float g_k [NTOK * DMODEL];
__device__ __align__(16) float g_v [NTOK * DMODEL];
__device__ __align__(16) float g_cg[NTOK * CEDIM];
__device__ __align__(16) float g_cv[NTOK * DMODEL];
__device__ __align__(16) float g_probs_spill[PROB_ELEMS];

// transposed weights (n-major, [N][K])
__device__ __align__(16) float g_ff1w1t[FFDIM * DMODEL];
__device__ __align__(16) float g_ff1w2t[DMODEL * FFDIM];
__device__ __align__(16) float g_ff2w1t[FFDIM * DMODEL];
__device__ __align__(16) float g_ff2w2t[DMODEL * FFDIM];
__device__ __align__(16) float g_wqt[DMODEL * DMODEL];
__device__ __align__(16) float g_wkt[DMODEL * DMODEL];
__device__ __align__(16) float g_wvt[DMODEL * DMODEL];
__device__ __align__(16) float g_pw1t[CEDIM * DMODEL];
__device__ __align__(16) float g_pw2t[DMODEL * DMODEL];

// ---------------------------------------------------------------- helpers
__device__ __forceinline__ float warp_sum(float v) {
    #pragma unroll
    for (int o = 16; o > 0; o >>= 1) v += __shfl_xor_sync(0xffffffffu, v, o);
    return v;
}
__device__ __forceinline__ float warp_max(float v) {
    #pragma unroll
    for (int o = 16; o > 0; o >>= 1) v = fmaxf(v, __shfl_xor_sync(0xffffffffu, v, o));
    return v;
}
__device__ __forceinline__ float swishf(float x) {
    return x / (1.0f + expf(-x));
}
__device__ __forceinline__ void mma_tf32(float c[4], const uint32_t a[4], const uint32_t b[2]) {
    asm volatile(
        "mma.sync.aligned.m16n8k8.row.col.f32.tf32.tf32.f32 "
        "{%0,%1,%2,%3}, {%4,%5,%6,%7}, {%8,%9}, {%0,%1,%2,%3};"
        : "+f"(c[0]), "+f"(c[1]), "+f"(c[2]), "+f"(c[3])
        : "r"(a[0]), "r"(a[1]), "r"(a[2]), "r"(a[3]), "r"(b[0]), "r"(b[1]));
}
__device__ __forceinline__ void ldsm4(uint32_t& r0, uint32_t& r1, uint32_t& r2, uint32_t& r3,
                                      uint32_t addr) {
    asm volatile("ldmatrix.sync.aligned.m8n8.x4.shared.b16 {%0,%1,%2,%3}, [%4];"
                 : "=r"(r0), "=r"(r1), "=r"(r2), "=r"(r3) : "r"(addr));
}
__device__ __forceinline__ void cp16(uint32_t dst_smem, const void* src) {
    asm volatile("cp.async.cg.shared.global [%0], [%1], 16;"
                 :: "r"(dst_smem), "l"(src));
}
__device__ __forceinline__ void cp_commit() {
    asm volatile("cp.async.commit_group;");
}
__device__ __forceinline__ void cp_wait1() {
    asm volatile("cp.async.wait_group 1;");
}

// ---------------------------------------------------------------- transpose
// out[C][R] = in[R][C]^T ; R,C multiples of 32
__global__ void transpose_kernel(const float* __restrict__ in, float* __restrict__ out,
                                 int R, int C) {
    __shared__ float tile[32][33];
    int bx = blockIdx.x * 32, by = blockIdx.y * 32;
    int tx = threadIdx.x, ty = threadIdx.y;   // 32 x 8
    #pragma unroll
    for (int i = 0; i < 32; i += 8)
        tile[ty + i][tx] = in[(size_t)(by + ty + i) * C + bx + tx];
    __syncthreads();
    #pragma unroll
    for (int i = 0; i < 32; i += 8)
        out[(size_t)(bx + ty + i) * R + by + tx] = tile[tx][ty + i];
}

// ---------------------------------------------------------------- tf32 GEMM
// C[M,N] = epilogue(A[M,K] @ Bt[N,K]^T + bias[N])   (Bt is n-major)
// MODE 0: bias only     MODE 1: swish(.)     MODE 2: res + scale*(.)
// 128x128 CTA tile, BK=16, 3-stage cp.async, ldmatrix fragments.
template <int MODE>
__device__ __forceinline__
void gemm_body(const float* __restrict__ A, const float* __restrict__ Bt,
               const float* __restrict__ bias, const float* __restrict__ res,
               float scale, float* __restrict__ C,
               int M, int N, int K, int bm, int bn) {
    __shared__ __align__(16) uint32_t As[3][128][16];   // 24 KB
    __shared__ __align__(16) uint32_t Bs[3][128][16];   // 24 KB (n-major)

    int tid  = threadIdx.x;
    int lane = tid & 31, wid = tid >> 5;
    int g = lane >> 2, tg = lane & 3;
    int m0w = (wid >> 1) * 32;
    int n0w = (wid & 1) * 64;

    // cp.async mapping (identical for As and Bs): 128 rows x 16 words/stage,
    // thread covers rows tid>>2 and (tid>>2)+64, word chunk (tid&3)*4.
    int r0c = tid >> 2, wc = (tid & 3) * 4;
    int r1c = r0c + 64;
    int off0 = r0c * 16 + (wc ^ ((r0c & 6) << 1));
    int off1 = r1c * 16 + (wc ^ ((r1c & 6) << 1));

    const float* a0src = A  + (size_t)(bm + r0c) * K + wc;
    const float* a1src = A  + (size_t)(bm + r1c) * K + wc;
    const float* b0src = Bt + (size_t)(bn + r0c) * K + wc;
    const float* b1src = Bt + (size_t)(bn + r1c) * K + wc;

    uint32_t sA = (uint32_t)__cvta_generic_to_shared(&As[0][0][0]);
    uint32_t sB = (uint32_t)__cvta_generic_to_shared(&Bs[0][0][0]);
    const int ST = 128 * 16 * 4;   // stage stride bytes

    // ldmatrix per-lane address terms
    int st  = lane >> 3;       // subtile id 0..3
    int rIn = lane & 7;
    int arow = m0w + ((st & 1) * 8) + rIn;       // + mt*16
    int asw  = (arow & 6) << 1;
    int aadd = (st >> 1) * 4;                    // k-chunk add
    int brow = n0w + ((st >> 1) * 8) + rIn;      // + p*16
    int bsw  = (brow & 6) << 1;
    int badd = (st & 1) * 4;

    float acc[2][8][4];
    #pragma unroll
    for (int mt = 0; mt < 2; mt++)
        #pragma unroll
        for (int nt = 0; nt < 8; nt++)
            #pragma unroll
            for (int i = 0; i < 4; i++) acc[mt][nt][i] = 0.0f;

    cp16(sA + 0 * ST + off0 * 4, a0src);
    cp16(sA + 0 * ST + off1 * 4, a1src);
    cp16(sB + 0 * ST + off0 * 4, b0src);
    cp16(sB + 0 * ST + off1 * 4, b1src);
    cp_commit();
    cp16(sA + 1 * ST + off0 * 4, a0src + 16);
    cp16(sA + 1 * ST + off1 * 4, a1src + 16);
    cp16(sB + 1 * ST + off0 * 4, b0src + 16);
    cp16(sB + 1 * ST + off1 * 4, b1src + 16);
    cp_commit();

    int niter = K / 16;
    int p = 0;
    for (int it = 0; it < niter; it++) {
        cp_wait1();
        __syncthreads();

        int kf = (it + 2) * 16;
        if (kf < K) {
            int pf = p + 2; if (pf >= 3) pf -= 3;
            cp16(sA + pf * ST + off0 * 4, a0src + kf);
            cp16(sA + pf * ST + off1 * 4, a1src + kf);
            cp16(sB + pf * ST + off0 * 4, b0src + kf);
            cp16(sB + pf * ST + off1 * 4, b1src + kf);
        }
        cp_commit();

        uint32_t stA = sA + p * ST;
        uint32_t stB = sB + p * ST;
        #pragma unroll
        for (int kk = 0; kk < 16; kk += 8) {
            uint32_t af[2][4], bf[8][2];
            #pragma unroll
            for (int mt = 0; mt < 2; mt++) {
                int row = arow + mt * 16;
                uint32_t ad = stA + (row * 16 + ((kk + aadd) ^ asw)) * 4;
                ldsm4(af[mt][0], af[mt][1], af[mt][2], af[mt][3], ad);
            }
            #pragma unroll
            for (int pp = 0; pp < 4; pp++) {
                int row = brow + pp * 16;
                uint32_t bd = stB + (row * 16 + ((kk + badd) ^ bsw)) * 4;
                ldsm4(bf[2 * pp][0], bf[2 * pp][1], bf[2 * pp + 1][0], bf[2 * pp + 1][1], bd);
            }
            #pragma unroll
            for (int mt = 0; mt < 2; mt++)
                #pragma unroll
                for (int nt = 0; nt < 8; nt++)
                    mma_tf32(acc[mt][nt], af[mt], bf[nt]);
        }
        p++; if (p >= 3) p = 0;
    }

    #pragma unroll
    for (int mt = 0; mt < 2; mt++) {
        int row0 = bm + m0w + mt * 16 + g;
        #pragma unroll
        for (int nt = 0; nt < 8; nt++) {
            int col = bn + n0w + nt * 8 + tg * 2;
            float bb0 = bias[col], bb1 = bias[col + 1];
            float v0 = acc[mt][nt][0] + bb0;
            float v1 = acc[mt][nt][1] + bb1;
            float v2 = acc[mt][nt][2] + bb0;
            float v3 = acc[mt][nt][3] + bb1;
            if (MODE == 1) {
                v0 = swishf(v0); v1 = swishf(v1); v2 = swishf(v2); v3 = swishf(v3);
            }
            if (MODE == 2) {
                const float* r0p = res + (size_t)row0 * N + col;
                const float* r1p = res + (size_t)(row0 + 8) * N + col;
                v0 = r0p[0] + scale * v0;
                v1 = r0p[1] + scale * v1;
                v2 = r1p[0] + scale * v2;
                v3 = r1p[1] + scale * v3;
            }
            *(float2*)(C + (size_t)row0 * N + col)       = make_float2(v0, v1);
            *(float2*)(C + (size_t)(row0 + 8) * N + col) = make_float2(v2, v3);
        }
    }
}

template <int MODE>
__global__ __launch_bounds__(256, 2)
void gemm_tf32(const float* __restrict__ A, const float* __restrict__ Bt,
               const float* __restrict__ bias, const float* __restrict__ res,
               float scale, float* __restrict__ C, int M, int N, int K) {
    gemm_body<MODE>(A, Bt, bias, res, scale, C, M, N, K,
                    blockIdx.y * 128, blockIdx.x * 128);
}

struct QKVArgs {
    const float* wt[3];
    const float* b[3];
    float* o[3];
};

__global__ __launch_bounds__(256, 2)
void gemm_tf32_qkv(QKVArgs args, const float* __restrict__ A, int M, int N, int K) {
    int z = blockIdx.z;
    gemm_body<0>(A, args.wt[z], args.b[z], nullptr, 0.0f, args.o[z],
                 M, N, K, blockIdx.y * 128, blockIdx.x * 128);
}

// ---------------------------------------------------------------- LayerNorm
__global__ void ln_kernel(const float* __restrict__ x,
                          const float* __restrict__ g,
                          const float* __restrict__ b,
                          float* __restrict__ out) {
    int row = blockIdx.x;
    int tid = threadIdx.x;
    const float* xr = x + (size_t)row * DMODEL;
    float v0 = xr[tid], v1 = xr[tid + 256];
    float s = v0 + v1;
    float q = v0 * v0 + v1 * v1;
    s = warp_sum(s);
    q = warp_sum(q);
    __shared__ float sh[16];
    int w = tid >> 5, l = tid & 31;
    if (l == 0) { sh[w] = s; sh[w + 8] = q; }
    __syncthreads();
    if (w == 0) {
        float a = (l < 8) ? sh[l] : 0.0f;
        float c = (l < 8) ? sh[l + 8] : 0.0f;
        a = warp_sum(a);
        c = warp_sum(c);
        if (l == 0) { sh[0] = a; sh[1] = c; }
    }
    __syncthreads();
    float mean = sh[0] * (1.0f / DMODEL);
    float var  = sh[1] * (1.0f / DMODEL) - mean * mean;
    float inv  = rsqrtf(var + 1e-5f);
    float* orow = out + (size_t)row * DMODEL;
    orow[tid]       = (v0 - mean) * inv * g[tid]       + b[tid];
    orow[tid + 256] = (v1 - mean) * inv * g[tid + 256] + b[tid + 256];
}

// ---------------------------------------------------------------- attention
__global__ __launch_bounds__(256)
void attn_kernel(const float* __restrict__ q, const float* __restrict__ k,
                 const float* __restrict__ v, float* __restrict__ h,
                 float* __restrict__ probs) {
    int row = blockIdx.x;             // 0..4095
    int t = row & (TSEQ - 1);
    int bstart = row - t;             // b*T
    int head = threadIdx.x >> 5;
    int lane = threadIdx.x & 31;
    int d0 = lane * 2;
    int base = row * DMODEL + head * DHEAD;

    float q0 = q[base + d0] * 0.125f;
    float q1 = q[base + d0 + 1] * 0.125f;

    __shared__ float sc[NHEAD][WB + 3];
    float* scrow = sc[head];

    float sgrp[2];
    #pragma unroll
    for (int gsel = 0; gsel < 2; gsel++) {
        int wbase = gsel * 32;
        float acc[32];
        #pragma unroll
        for (int w = 0; w < 32; w++) {
            int pos = t + wbase + w - 32;
            float k0 = 0.0f, k1 = 0.0f;
            if (pos >= 0 && pos < TSEQ) {
                float2 kv = *(const float2*)&k[(size_t)(bstart + pos) * DMODEL + head * DHEAD + d0];
                k0 = kv.x; k1 = kv.y;
            }
            acc[w] = q0 * k0 + q1 * k1;
        }
        int n = 32;
        #pragma unroll
        for (int off = 16; off >= 1; off >>= 1) {
            bool upper = (lane & off) != 0;
            #pragma unroll
            for (int j = 0; j < 16; j++) {
                if (j < n / 2) {
                    float send = upper ? acc[j] : acc[j + n / 2];
                    float recv = __shfl_xor_sync(0xffffffffu, send, off);
                    acc[j] = (upper ? acc[j + n / 2] : acc[j]) + recv;
                }
            }
            n >>= 1;
        }
        int posW = t + wbase + lane - 32;
        sgrp[gsel] = (posW >= 0 && posW < TSEQ) ? acc[0] : -1e9f;
    }

    float s64;
    {
        int pos = t + 32;
        float p = 0.0f;
        if (pos < TSEQ) {
            float2 kv = *(const float2*)&k[(size_t)(bstart + pos) * DMODEL + head * DHEAD + d0];
            p = q0 * kv.x + q1 * kv.y;
        }
        p = warp_sum(p);
        s64 = (pos < TSEQ) ? p : -1e9f;
    }

    float m = fmaxf(fmaxf(sgrp[0], sgrp[1]), s64);
    m = warp_max(m);
    float e0 = expf(sgrp[0] - m);
    float e1 = expf(sgrp[1] - m);
    float e64 = expf(s64 - m);
    float sum = warp_sum(e0 + e1) + e64;
    float inv = 1.0f / sum;
    float p0 = e0 * inv, p1 = e1 * inv, p64 = e64 * inv;

    float* prow = probs + ((size_t)row * NHEAD + head) * WB;
    scrow[lane] = p0;
    scrow[lane + 32] = p1;
    prow[lane] = p0;
    prow[lane + 32] = p1;
    if (lane == 0) { scrow[64] = p64; prow[64] = p64; }
    __syncwarp();

    float a0 = 0.0f, a1 = 0.0f;
    for (int w = 0; w < WB; w++) {
        int pos = t + w - 32;
        if (pos >= 0 && pos < TSEQ) {
            float pr = scrow[w];
            float2 vv = *(const float2*)&v[(size_t)(bstart + pos) * DMODEL + head * DHEAD + d0];
            a0 = fmaf(pr, vv.x, a0);
            a1 = fmaf(pr, vv.y, a1);
        }
    }
    h[base + d0]     += a0;
    h[base + d0 + 1] += a1;
}

// ---------------------------------------- fused GLU + depthwise conv + BN + swish
#define DW_TOK 64
#define DW_CH  128
__global__ __launch_bounds__(256)
void glu_dwconv_kernel(const float* __restrict__ cg,
                       const float* __restrict__ dw_w,
                       const float* __restrict__ dw_b,
                       const float* __restrict__ bn_g,
                       const float* __restrict__ bn_b,
                       float* __restrict__ out) {
    __shared__ float s[DW_TOK + KSIZE - 1][DW_CH];   // 94 x 128 = 47 KB
    int ct = blockIdx.x * DW_CH;
    int tt = blockIdx.y * DW_TOK;
    int t0 = tt & (TSEQ - 1);
    int bstart = tt - t0;
    int tid = threadIdx.x;

    for (int i = tid; i < (DW_TOK + KSIZE - 1) * DW_CH; i += 256) {
        int r = i >> 7;
        int c = i & (DW_CH - 1);
        int pos = t0 + r - 15;
        float val = 0.0f;
        if (pos >= 0 && pos < TSEQ) {
            const float* cgrow = cg + (size_t)(bstart + pos) * CEDIM;
            float a = cgrow[ct + c];
            float gate = cgrow[DMODEL + ct + c];
            val = a / (1.0f + expf(-gate));
        }
        s[r][c] = val;
    }
    __syncthreads();

    int c = tid & (DW_CH - 1);
    int trow = tid >> 7;
    float wreg[KSIZE];
    #pragma unroll
    for (int j = 0; j < KSIZE; j++) wreg[j] = dw_w[j * DMODEL + ct + c];
    float bb = dw_b[ct + c];
    float bg = bn_g[ct + c] * rsqrtf(1.0f + 1e-5f);
    float bbn = bn_b[ct + c];

    #pragma unroll 4
    for (int i = 0; i < DW_TOK / 2; i++) {
        int lt = trow + 2 * i;
        float acc = 0.0f;
        #pragma unroll
        for (int j = 0; j < KSIZE; j++)
            acc = fmaf(s[lt + j][c], wreg[j], acc);
        acc += bb;
        float hx = acc * bg + bbn;
        out[(size_t)(tt + lt) * DMODEL + ct + c] = swishf(hx);
    }
}

// ---------------------------------------------------------------- launch
static inline dim3 gemm_grid(int M, int N) { return dim3(N / 128, M / 128); }
static inline dim3 tr_grid(int R, int C) { return dim3(C / 32, R / 32); }

extern "C" void kernel_launch(void* const* d_in, const int* in_sizes, int n_in,
                              void* d_out, int out_size) {
    const float* x          = (const float*)d_in[0];
    const float* ff1_ln_g   = (const float*)d_in[1];
    const float* ff1_ln_b   = (const float*)d_in[2];
    const float* ff1_w1     = (const float*)d_in[3];
    const float* ff1_b1     = (const float*)d_in[4];
    const float* ff1_w2     = (const float*)d_in[5];
    const float* ff1_b2     = (const float*)d_in[6];
    const float* ff2_ln_g   = (const float*)d_in[7];
    const float* ff2_ln_b   = (const float*)d_in[8];
    const float* ff2_w1     = (const float*)d_in[9];
    const float* ff2_b1     = (const float*)d_in[10];
    const float* ff2_w2     = (const float*)d_in[11];
    const float* ff2_b2     = (const float*)d_in[12];
    const float* wq         = (const float*)d_in[13];
    const float* bq         = (const float*)d_in[14];
    const float* wk         = (const float*)d_in[15];
    const float* bk         = (const float*)d_in[16];
    const float* wv         = (const float*)d_in[17];
    const float* bv         = (const float*)d_in[18];
    const float* conv_ln_g  = (const float*)d_in[19];
    const float* conv_ln_b  = (const float*)d_in[20];
    const float* conv_pw1_w = (const float*)d_in[21];
    const float* conv_pw1_b = (const float*)d_in[22];
    const float* conv_dw_w  = (const float*)d_in[23];
    const float* conv_dw_b  = (const float*)d_in[24];
    const float* conv_bn_g  = (const float*)d_in[25];
    const float* conv_bn_b  = (const float*)d_in[26];
    const float* conv_pw2_w = (const float*)d_in[27];
    const float* conv_pw2_b = (const float*)d_in[28];
    const float* final_ln_g = (const float*)d_in[29];
    const float* final_ln_b = (const float*)d_in[30];

    float *xn, *h, *ff, *q, *k, *v, *cg, *cv, *pspill;
    float *ff1w1t, *ff1w2t, *ff2w1t, *ff2w2t, *wqt, *wkt, *wvt, *pw1t, *pw2t;
    cudaGetSymbolAddress((void**)&xn, g_xn);
    cudaGetSymbolAddress((void**)&h,  g_h);
    cudaGetSymbolAddress((void**)&ff, g_ff);
    cudaGetSymbolAddress((void**)&q,  g_q);
    cudaGetSymbolAddress((void**)&k,  g_k);
    cudaGetSymbolAddress((void**)&v,  g_v);
    cudaGetSymbolAddress((void**)&cg, g_cg);
    cudaGetSymbolAddress((void**)&cv, g_cv);
    cudaGetSymbolAddress((void**)&pspill, g_probs_spill);
    cudaGetSymbolAddress((void**)&ff1w1t, g_ff1w1t);
    cudaGetSymbolAddress((void**)&ff1w2t, g_ff1w2t);
    cudaGetSymbolAddress((void**)&ff2w1t, g_ff2w1t);
    cudaGetSymbolAddress((void**)&ff2w2t, g_ff2w2t);
    cudaGetSymbolAddress((void**)&wqt, g_wqt);
    cudaGetSymbolAddress((void**)&wkt, g_wkt);
    cudaGetSymbolAddress((void**)&wvt, g_wvt);
    cudaGetSymbolAddress((void**)&pw1t, g_pw1t);
    cudaGetSymbolAddress((void**)&pw2t, g_pw2t);

    float* out_main  = (float*)d_out;
    float* out_probs = (out_size >= OUT_ELEMS + PROB_ELEMS)
                         ? (float*)d_out + OUT_ELEMS : pspill;

    dim3 trb(32, 8);
    // weight transposes (w[K][N] -> wt[N][K])
    transpose_kernel<<<tr_grid(DMODEL, FFDIM), trb>>>(ff1_w1, ff1w1t, DMODEL, FFDIM);
    transpose_kernel<<<tr_grid(FFDIM, DMODEL), trb>>>(ff1_w2, ff1w2t, FFDIM, DMODEL);
    transpose_kernel<<<tr_grid(DMODEL, FFDIM), trb>>>(ff2_w1, ff2w1t, DMODEL, FFDIM);
    transpose_kernel<<<tr_grid(FFDIM, DMODEL), trb>>>(ff2_w2, ff2w2t, FFDIM, DMODEL);
    transpose_kernel<<<tr_grid(DMODEL, DMODEL), trb>>>(wq, wqt, DMODEL, DMODEL);
    transpose_kernel<<<tr_grid(DMODEL, DMODEL), trb>>>(wk, wkt, DMODEL, DMODEL);
    transpose_kernel<<<tr_grid(DMODEL, DMODEL), trb>>>(wv, wvt, DMODEL, DMODEL);
    transpose_kernel<<<tr_grid(DMODEL, CEDIM), trb>>>(conv_pw1_w, pw1t, DMODEL, CEDIM);
    transpose_kernel<<<tr_grid(DMODEL, DMODEL), trb>>>(conv_pw2_w, pw2t, DMODEL, DMODEL);

    // ---- FF1: h = x + 0.5 * (swish(LN(x)@w1+b1) @ w2 + b2)
    ln_kernel<<<NTOK, 256>>>(x, ff1_ln_g, ff1_ln_b, xn);
    gemm_tf32<1><<<gemm_grid(NTOK, FFDIM), 256>>>(xn, ff1w1t, ff1_b1, nullptr, 0.f,
                                                  ff, NTOK, FFDIM, DMODEL);
    gemm_tf32<2><<<gemm_grid(NTOK, DMODEL), 256>>>(ff, ff1w2t, ff1_b2, x, 0.5f,
                                                   h, NTOK, DMODEL, FFDIM);

    // ---- attention
    {
        QKVArgs args;
        args.wt[0] = wqt; args.wt[1] = wkt; args.wt[2] = wvt;
        args.b[0] = bq;   args.b[1] = bk;   args.b[2] = bv;
        args.o[0] = q;    args.o[1] = k;    args.o[2] = v;
        dim3 grid(DMODEL / 128, NTOK / 128, 3);
        gemm_tf32_qkv<<<grid, 256>>>(args, h, NTOK, DMODEL, DMODEL);
    }
    attn_kernel<<<NTOK, 256>>>(q, k, v, h, out_probs);

    // ---- conv module
    ln_kernel<<<NTOK, 256>>>(h, conv_ln_g, conv_ln_b, xn);
    gemm_tf32<0><<<gemm_grid(NTOK, CEDIM), 256>>>(xn, pw1t, conv_pw1_b, nullptr, 0.f,
                                                  cg, NTOK, CEDIM, DMODEL);
    {
        dim3 grid(DMODEL / DW_CH, NTOK / DW_TOK);
        glu_dwconv_kernel<<<grid, 256>>>(cg, conv_dw_w, conv_dw_b,
                                         conv_bn_g, conv_bn_b, cv);
    }
    gemm_tf32<2><<<gemm_grid(NTOK, DMODEL), 256>>>(cv, pw2t, conv_pw2_b, h, 1.0f,
                                                   h, NTOK, DMODEL, DMODEL);

    // ---- FF2
    ln_kernel<<<NTOK, 256>>>(h, ff2_ln_g, ff2_ln_b, xn);
    gemm_tf32<1><<<gemm_grid(NTOK, FFDIM), 256>>>(xn, ff2w1t, ff2_b1, nullptr, 0.f,
                                                  ff, NTOK, FFDIM, DMODEL);
    gemm_tf32<2><<<gemm_grid(NTOK, DMODEL), 256>>>(ff, ff2w2t, ff2_b2, h, 0.5f,
                                                   h, NTOK, DMODEL, FFDIM);

    // ---- final LN -> out
    ln_kernel<<<NTOK, 256>>>(h, final_ln_g, final_ln_b, out_main);
}

// round 8
// speedup vs baseline: 4.8669x; 1.3099x over previous
#include <cuda_runtime.h>
#include <cuda_fp16.h>
#include <math.h>
#include <stdint.h>

// ----------------------------------------------------------------------------
// ConformerBlock: B=4, T=1024, D=512, H=8, DH=64, W1=32, WB=65, FF=2048,
// CE=1024, KS=31.
// GEMMs: fp16 mma.sync m16n8k16 (fp32 accum), cp.async 3-stage BK=32,
// ldmatrix fragments, weights pre-transposed+converted to fp16 n-major.
// Residual stream / attention / conv math stays fp32.
// ----------------------------------------------------------------------------

#define NTOK   4096          // B*T
#define DMODEL 512
#define TSEQ   1024
#define NHEAD  8
#define DHEAD  64
#define WB     65
#define FFDIM  2048
#define CEDIM  1024
#define KSIZE  31
#define OUT_ELEMS   (NTOK * DMODEL)          // 2097152
#define PROB_ELEMS  (NTOK * NHEAD * WB)      // 2129920

// ---- scratch (static device memory; no allocations allowed) ----
__device__ __align__(16) __half g_xn [NTOK * DMODEL];   // LN outputs (GEMM A)
__device__ __align__(16) float  g_h  [NTOK * DMODEL];   // fp32 residual stream
__device__ __align__(16) __half g_h16[NTOK * DMODEL];   // h shadow for QKV A
__device__ __align__(16) __half g_ff [NTOK * FFDIM];    // FF hidden (GEMM A)
__device__ __align__(16) float  g_q  [NTOK * DMODEL];
__device__ __align__(16) float  g_k  [NTOK * DMODEL];
__device__ __align__(16) float  g_v  [NTOK * DMODEL];
__device__ __align__(16) float  g_cg [NTOK * CEDIM];
__device__ __align__(16) __half g_cv [NTOK * DMODEL];   // conv out (GEMM A)
__device__ __align__(16) float  g_probs_spill[PROB_ELEMS];

// transposed fp16 weights (n-major, [N][K])
__device__ __align__(16) __half g_ff1w1t[FFDIM * DMODEL];
__device__ __align__(16) __half g_ff1w2t[DMODEL * FFDIM];
__device__ __align__(16) __half g_ff2w1t[FFDIM * DMODEL];
__device__ __align__(16) __half g_ff2w2t[DMODEL * FFDIM];
__device__ __align__(16) __half g_wqt[DMODEL * DMODEL];
__device__ __align__(16) __half g_wkt[DMODEL * DMODEL];
__device__ __align__(16) __half g_wvt[DMODEL * DMODEL];
__device__ __align__(16) __half g_pw1t[CEDIM * DMODEL];
__device__ __align__(16) __half g_pw2t[DMODEL * DMODEL];

// ---------------------------------------------------------------- helpers
__device__ __forceinline__ float warp_sum(float v) {
    #pragma unroll
    for (int o = 16; o > 0; o >>= 1) v += __shfl_xor_sync(0xffffffffu, v, o);
    return v;
}
__device__ __forceinline__ float warp_max(float v) {
    #pragma unroll
    for (int o = 16; o > 0; o >>= 1) v = fmaxf(v, __shfl_xor_sync(0xffffffffu, v, o));
    return v;
}
__device__ __forceinline__ float swishf(float x) {
    return x / (1.0f + expf(-x));
}
__device__ __forceinline__ void mma_f16(float c[4], const uint32_t a[4], const uint32_t b[2]) {
    asm volatile(
        "mma.sync.aligned.m16n8k16.row.col.f32.f16.f16.f32 "
        "{%0,%1,%2,%3}, {%4,%5,%6,%7}, {%8,%9}, {%0,%1,%2,%3};"
        : "+f"(c[0]), "+f"(c[1]), "+f"(c[2]), "+f"(c[3])
        : "r"(a[0]), "r"(a[1]), "r"(a[2]), "r"(a[3]), "r"(b[0]), "r"(b[1]));
}
__device__ __forceinline__ void ldsm4(uint32_t& r0, uint32_t& r1, uint32_t& r2, uint32_t& r3,
                                      uint32_t addr) {
    asm volatile("ldmatrix.sync.aligned.m8n8.x4.shared.b16 {%0,%1,%2,%3}, [%4];"
                 : "=r"(r0), "=r"(r1), "=r"(r2), "=r"(r3) : "r"(addr));
}
__device__ __forceinline__ void cp16(uint32_t dst_smem, const void* src) {
    asm volatile("cp.async.cg.shared.global [%0], [%1], 16;"
                 :: "r"(dst_smem), "l"(src));
}
__device__ __forceinline__ void cp_commit() {
    asm volatile("cp.async.commit_group;");
}
__device__ __forceinline__ void cp_wait1() {
    asm volatile("cp.async.wait_group 1;");
}

// ---------------------------------------------------------------- transpose+cvt
// out[C][R] (fp16) = in[R][C]^T ; R,C multiples of 32
__global__ void transpose_h_kernel(const float* __restrict__ in, __half* __restrict__ out,
                                   int R, int C) {
    __shared__ float tile[32][33];
    int bx = blockIdx.x * 32, by = blockIdx.y * 32;
    int tx = threadIdx.x, ty = threadIdx.y;   // 32 x 8
    #pragma unroll
    for (int i = 0; i < 32; i += 8)
        tile[ty + i][tx] = in[(size_t)(by + ty + i) * C + bx + tx];
    __syncthreads();
    #pragma unroll
    for (int i = 0; i < 32; i += 8)
        out[(size_t)(bx + ty + i) * R + by + tx] = __float2half_rn(tile[tx][ty + i]);
}

// ---------------------------------------------------------------- fp16 GEMM
// C = epilogue(A[M,K] @ Bt[N,K]^T + bias[N]);  A,Bt fp16, accum fp32.
// MODE 0: bias -> fp32 Cf
// MODE 1: swish(.) -> fp16 Ch
// MODE 2: res + scale*(.) -> fp32 Cf (+ optional fp16 copy C2)
// 128x128 CTA tile, BK=32, 3-stage cp.async, ldmatrix fragments.
// smem row = 32 halves = 4 chunks of 16B; swizzle: chunk ^= (row>>1)&3.
template <int MODE>
__device__ __forceinline__
void gemm_body(const __half* __restrict__ A, const __half* __restrict__ Bt,
               const float* __restrict__ bias, const float* __restrict__ res,
               float scale, float* __restrict__ Cf, __half* __restrict__ Ch,
               __half* __restrict__ C2,
               int M, int N, int K, int bm, int bn) {
    __shared__ __align__(16) uint32_t As[3][128][16];   // 8 KB/stage
    __shared__ __align__(16) uint32_t Bs[3][128][16];   // 8 KB/stage

    int tid  = threadIdx.x;
    int lane = tid & 31, wid = tid >> 5;
    int g = lane >> 2, tg = lane & 3;
    int m0w = (wid >> 1) * 32;
    int n0w = (wid & 1) * 64;

    // cp.async: 512 chunks (128 rows x 4) per tile; thread does chunks tid, tid+256
    int row0 = tid >> 2, c0 = tid & 3;
    int row1 = row0 + 64;
    int off0 = row0 * 16 + (c0 ^ ((row0 >> 1) & 3)) * 4;
    int off1 = row1 * 16 + (c0 ^ ((row1 >> 1) & 3)) * 4;

    const __half* a0src = A  + (size_t)(bm + row0) * K + c0 * 8;
    const __half* a1src = A  + (size_t)(bm + row1) * K + c0 * 8;
    const __half* b0src = Bt + (size_t)(bn + row0) * K + c0 * 8;
    const __half* b1src = Bt + (size_t)(bn + row1) * K + c0 * 8;

    uint32_t sA = (uint32_t)__cvta_generic_to_shared(&As[0][0][0]);
    uint32_t sB = (uint32_t)__cvta_generic_to_shared(&Bs[0][0][0]);
    const int ST = 128 * 16 * 4;   // 8192 B stage stride

    // ldmatrix lane terms: subtile st = lane>>3 (tiles: +0/+8 rows, +0/+1 chunk)
    int st  = lane >> 3;
    int rIn = lane & 7;
    int am  = m0w + (st & 1) * 8 + rIn;    // + mt*16
    int an0 = n0w + (st & 1) * 8 + rIn;    // + pp*16
    int cadd = st >> 1;                    // chunk add 0/1

    float acc[2][8][4];
    #pragma unroll
    for (int mt = 0; mt < 2; mt++)
        #pragma unroll
        for (int nt = 0; nt < 8; nt++)
            #pragma unroll
            for (int i = 0; i < 4; i++) acc[mt][nt][i] = 0.0f;

    cp16(sA + 0 * ST + off0 * 4, a0src);
    cp16(sA + 0 * ST + off1 * 4, a1src);
    cp16(sB + 0 * ST + off0 * 4, b0src);
    cp16(sB + 0 * ST + off1 * 4, b1src);
    cp_commit();
    cp16(sA + 1 * ST + off0 * 4, a0src + 32);
    cp16(sA + 1 * ST + off1 * 4, a1src + 32);
    cp16(sB + 1 * ST + off0 * 4, b0src + 32);
    cp16(sB + 1 * ST + off1 * 4, b1src + 32);
    cp_commit();

    int niter = K / 32;
    int p = 0;
    for (int it = 0; it < niter; it++) {
        cp_wait1();
        __syncthreads();

        int kf = (it + 2) * 32;
        if (kf < K) {
            int pf = p + 2; if (pf >= 3) pf -= 3;
            cp16(sA + pf * ST + off0 * 4, a0src + kf);
            cp16(sA + pf * ST + off1 * 4, a1src + kf);
            cp16(sB + pf * ST + off0 * 4, b0src + kf);
            cp16(sB + pf * ST + off1 * 4, b1src + kf);
        }
        cp_commit();

        uint32_t stA = sA + p * ST;
        uint32_t stB = sB + p * ST;
        #pragma unroll
        for (int ks = 0; ks < 2; ks++) {
            int kkc = ks * 2;
            uint32_t af[2][4], bf[8][2];
            #pragma unroll
            for (int mt = 0; mt < 2; mt++) {
                int row = am + mt * 16;
                int c = (kkc + cadd) ^ ((row >> 1) & 3);
                uint32_t ad = stA + (row * 16 + c * 4) * 4;
                ldsm4(af[mt][0], af[mt][1], af[mt][2], af[mt][3], ad);
            }
            #pragma unroll
            for (int pp = 0; pp < 4; pp++) {
                int row = an0 + pp * 16;
                int c = (kkc + cadd) ^ ((row >> 1) & 3);
                uint32_t bd = stB + (row * 16 + c * 4) * 4;
                ldsm4(bf[2 * pp][0], bf[2 * pp + 1][0], bf[2 * pp][1], bf[2 * pp + 1][1], bd);
            }
            #pragma unroll
            for (int mt = 0; mt < 2; mt++)
                #pragma unroll
                for (int nt = 0; nt < 8; nt++)
                    mma_f16(acc[mt][nt], af[mt], bf[nt]);
        }
        p++; if (p >= 3) p = 0;
    }

    // epilogue: acc[..][0,1] -> row g cols 2tg,2tg+1 ; acc[..][2,3] -> row g+8
    #pragma unroll
    for (int mt = 0; mt < 2; mt++) {
        int row0e = bm + m0w + mt * 16 + g;
        #pragma unroll
        for (int nt = 0; nt < 8; nt++) {
            int col = bn + n0w + nt * 8 + tg * 2;
            float bb0 = bias[col], bb1 = bias[col + 1];
            float v0 = acc[mt][nt][0] + bb0;
            float v1 = acc[mt][nt][1] + bb1;
            float v2 = acc[mt][nt][2] + bb0;
            float v3 = acc[mt][nt][3] + bb1;
            if (MODE == 1) {
                v0 = swishf(v0); v1 = swishf(v1); v2 = swishf(v2); v3 = swishf(v3);
                *(__half2*)(Ch + (size_t)row0e * N + col)       = __floats2half2_rn(v0, v1);
                *(__half2*)(Ch + (size_t)(row0e + 8) * N + col) = __floats2half2_rn(v2, v3);
            } else {
                if (MODE == 2) {
                    const float* r0p = res + (size_t)row0e * N + col;
                    const float* r1p = res + (size_t)(row0e + 8) * N + col;
                    v0 = r0p[0] + scale * v0;
                    v1 = r0p[1] + scale * v1;
                    v2 = r1p[0] + scale * v2;
                    v3 = r1p[1] + scale * v3;
                }
                *(float2*)(Cf + (size_t)row0e * N + col)       = make_float2(v0, v1);
                *(float2*)(Cf + (size_t)(row0e + 8) * N + col) = make_float2(v2, v3);
                if (MODE == 2 && C2 != nullptr) {
                    *(__half2*)(C2 + (size_t)row0e * N + col)       = __floats2half2_rn(v0, v1);
                    *(__half2*)(C2 + (size_t)(row0e + 8) * N + col) = __floats2half2_rn(v2, v3);
                }
            }
        }
    }
}

template <int MODE>
__global__ __launch_bounds__(256, 2)
void gemm_h(const __half* __restrict__ A, const __half* __restrict__ Bt,
            const float* __restrict__ bias, const float* __restrict__ res,
            float scale, float* __restrict__ Cf, __half* __restrict__ Ch,
            __half* __restrict__ C2, int M, int N, int K) {
    gemm_body<MODE>(A, Bt, bias, res, scale, Cf, Ch, C2, M, N, K,
                    blockIdx.y * 128, blockIdx.x * 128);
}

struct QKVArgs {
    const __half* wt[3];
    const float* b[3];
    float* o[3];
};

__global__ __launch_bounds__(256, 2)
void gemm_h_qkv(QKVArgs args, const __half* __restrict__ A, int M, int N, int K) {
    int z = blockIdx.z;
    gemm_body<0>(A, args.wt[z], args.b[z], nullptr, 0.0f, args.o[z], nullptr, nullptr,
                 M, N, K, blockIdx.y * 128, blockIdx.x * 128);
}

// ---------------------------------------------------------------- LayerNorm (fp16 out)
__global__ void ln_kernel(const float* __restrict__ x,
                          const float* __restrict__ g,
                          const float* __restrict__ b,
                          __half* __restrict__ out) {
    int row = blockIdx.x;
    int tid = threadIdx.x;
    const float* xr = x + (size_t)row * DMODEL;
    float v0 = xr[tid], v1 = xr[tid + 256];
    float s = v0 + v1;
    float q = v0 * v0 + v1 * v1;
    s = warp_sum(s);
    q = warp_sum(q);
    __shared__ float sh[16];
    int w = tid >> 5, l = tid & 31;
    if (l == 0) { sh[w] = s; sh[w + 8] = q; }
    __syncthreads();
    if (w == 0) {
        float a = (l < 8) ? sh[l] : 0.0f;
        float c = (l < 8) ? sh[l + 8] : 0.0f;
        a = warp_sum(a);
        c = warp_sum(c);
        if (l == 0) { sh[0] = a; sh[1] = c; }
    }
    __syncthreads();
    float mean = sh[0] * (1.0f / DMODEL);
    float var  = sh[1] * (1.0f / DMODEL) - mean * mean;
    float inv  = rsqrtf(var + 1e-5f);
    __half* orow = out + (size_t)row * DMODEL;
    orow[tid]       = __float2half_rn((v0 - mean) * inv * g[tid]       + b[tid]);
    orow[tid + 256] = __float2half_rn((v1 - mean) * inv * g[tid + 256] + b[tid + 256]);
}

// final LN keeps fp32 output
__global__ void ln_f32_kernel(const float* __restrict__ x,
                              const float* __restrict__ g,
                              const float* __restrict__ b,
                              float* __restrict__ out) {
    int row = blockIdx.x;
    int tid = threadIdx.x;
    const float* xr = x + (size_t)row * DMODEL;
    float v0 = xr[tid], v1 = xr[tid + 256];
    float s = v0 + v1;
    float q = v0 * v0 + v1 * v1;
    s = warp_sum(s);
    q = warp_sum(q);
    __shared__ float sh[16];
    int w = tid >> 5, l = tid & 31;
    if (l == 0) { sh[w] = s; sh[w + 8] = q; }
    __syncthreads();
    if (w == 0) {
        float a = (l < 8) ? sh[l] : 0.0f;
        float c = (l < 8) ? sh[l + 8] : 0.0f;
        a = warp_sum(a);
        c = warp_sum(c);
        if (l == 0) { sh[0] = a; sh[1] = c; }
    }
    __syncthreads();
    float mean = sh[0] * (1.0f / DMODEL);
    float var  = sh[1] * (1.0f / DMODEL) - mean * mean;
    float inv  = rsqrtf(var + 1e-5f);
    float* orow = out + (size_t)row * DMODEL;
    orow[tid]       = (v0 - mean) * inv * g[tid]       + b[tid];
    orow[tid + 256] = (v1 - mean) * inv * g[tid + 256] + b[tid + 256];
}

// ---------------------------------------------------------------- attention (fp32)
__global__ __launch_bounds__(256)
void attn_kernel(const float* __restrict__ q, const float* __restrict__ k,
                 const float* __restrict__ v, float* __restrict__ h,
                 float* __restrict__ probs) {
    int row = blockIdx.x;             // 0..4095
    int t = row & (TSEQ - 1);
    int bstart = row - t;             // b*T
    int head = threadIdx.x >> 5;
    int lane = threadIdx.x & 31;
    int d0 = lane * 2;
    int base = row * DMODEL + head * DHEAD;

    float q0 = q[base + d0] * 0.125f;
    float q1 = q[base + d0 + 1] * 0.125f;

    __shared__ float sc[NHEAD][WB + 3];
    float* scrow = sc[head];

    float sgrp[2];
    #pragma unroll
    for (int gsel = 0; gsel < 2; gsel++) {
        int wbase = gsel * 32;
        float acc[32];
        #pragma unroll
        for (int w = 0; w < 32; w++) {
            int pos = t + wbase + w - 32;
            float k0 = 0.0f, k1 = 0.0f;
            if (pos >= 0 && pos < TSEQ) {
                float2 kv = *(const float2*)&k[(size_t)(bstart + pos) * DMODEL + head * DHEAD + d0];
                k0 = kv.x; k1 = kv.y;
            }
            acc[w] = q0 * k0 + q1 * k1;
        }
        int n = 32;
        #pragma unroll
        for (int off = 16; off >= 1; off >>= 1) {
            bool upper = (lane & off) != 0;
            #pragma unroll
            for (int j = 0; j < 16; j++) {
                if (j < n / 2) {
                    float send = upper ? acc[j] : acc[j + n / 2];
                    float recv = __shfl_xor_sync(0xffffffffu, send, off);
                    acc[j] = (upper ? acc[j + n / 2] : acc[j]) + recv;
                }
            }
            n >>= 1;
        }
        int posW = t + wbase + lane - 32;
        sgrp[gsel] = (posW >= 0 && posW < TSEQ) ? acc[0] : -1e9f;
    }

    float s64;
    {
        int pos = t + 32;
        float p = 0.0f;
        if (pos < TSEQ) {
            float2 kv = *(const float2*)&k[(size_t)(bstart + pos) * DMODEL + head * DHEAD + d0];
            p = q0 * kv.x + q1 * kv.y;
        }
        p = warp_sum(p);
        s64 = (pos < TSEQ) ? p : -1e9f;
    }

    float m = fmaxf(fmaxf(sgrp[0], sgrp[1]), s64);
    m = warp_max(m);
    float e0 = expf(sgrp[0] - m);
    float e1 = expf(sgrp[1] - m);
    float e64 = expf(s64 - m);
    float sum = warp_sum(e0 + e1) + e64;
    float inv = 1.0f / sum;
    float p0 = e0 * inv, p1 = e1 * inv, p64 = e64 * inv;

    float* prow = probs + ((size_t)row * NHEAD + head) * WB;
    scrow[lane] = p0;
    scrow[lane + 32] = p1;
    prow[lane] = p0;
    prow[lane + 32] = p1;
    if (lane == 0) { scrow[64] = p64; prow[64] = p64; }
    __syncwarp();

    float a0 = 0.0f, a1 = 0.0f;
    for (int w = 0; w < WB; w++) {
        int pos = t + w - 32;
        if (pos >= 0 && pos < TSEQ) {
            float pr = scrow[w];
            float2 vv = *(const float2*)&v[(size_t)(bstart + pos) * DMODEL + head * DHEAD + d0];
            a0 = fmaf(pr, vv.x, a0);
            a1 = fmaf(pr, vv.y, a1);
        }
    }
    h[base + d0]     += a0;
    h[base + d0 + 1] += a1;
}

// ---------------------------------------- fused GLU + depthwise conv + BN + swish
#define DW_TOK 64
#define DW_CH  128
__global__ __launch_bounds__(256)
void glu_dwconv_kernel(const float* __restrict__ cg,
                       const float* __restrict__ dw_w,
                       const float* __restrict__ dw_b,
                       const float* __restrict__ bn_g,
                       const float* __restrict__ bn_b,
                       __half* __restrict__ out) {
    __shared__ float s[DW_TOK + KSIZE - 1][DW_CH];   // 94 x 128 = 47 KB
    int ct = blockIdx.x * DW_CH;
    int tt = blockIdx.y * DW_TOK;
    int t0 = tt & (TSEQ - 1);
    int bstart = tt - t0;
    int tid = threadIdx.x;

    for (int i = tid; i < (DW_TOK + KSIZE - 1) * DW_CH; i += 256) {
        int r = i >> 7;
        int c = i & (DW_CH - 1);
        int pos = t0 + r - 15;
        float val = 0.0f;
        if (pos >= 0 && pos < TSEQ) {
            const float* cgrow = cg + (size_t)(bstart + pos) * CEDIM;
            float a = cgrow[ct + c];
            float gate = cgrow[DMODEL + ct + c];
            val = a / (1.0f + expf(-gate));
        }
        s[r][c] = val;
    }
    __syncthreads();

    int c = tid & (DW_CH - 1);
    int trow = tid >> 7;
    float wreg[KSIZE];
    #pragma unroll
    for (int j = 0; j < KSIZE; j++) wreg[j] = dw_w[j * DMODEL + ct + c];
    float bb = dw_b[ct + c];
    float bg = bn_g[ct + c] * rsqrtf(1.0f + 1e-5f);
    float bbn = bn_b[ct + c];

    #pragma unroll 4
    for (int i = 0; i < DW_TOK / 2; i++) {
        int lt = trow + 2 * i;
        float acc = 0.0f;
        #pragma unroll
        for (int j = 0; j < KSIZE; j++)
            acc = fmaf(s[lt + j][c], wreg[j], acc);
        acc += bb;
        float hx = acc * bg + bbn;
        out[(size_t)(tt + lt) * DMODEL + ct + c] = __float2half_rn(swishf(hx));
    }
}

// ---------------------------------------------------------------- launch
static inline dim3 gemm_grid(int M, int N) { return dim3(N / 128, M / 128); }
static inline dim3 tr_grid(int R, int C) { return dim3(C / 32, R / 32); }

extern "C" void kernel_launch(void* const* d_in, const int* in_sizes, int n_in,
                              void* d_out, int out_size) {
    const float* x          = (const float*)d_in[0];
    const float* ff1_ln_g   = (const float*)d_in[1];
    const float* ff1_ln_b   = (const float*)d_in[2];
    const float* ff1_w1     = (const float*)d_in[3];
    const float* ff1_b1     = (const float*)d_in[4];
    const float* ff1_w2     = (const float*)d_in[5];
    const float* ff1_b2     = (const float*)d_in[6];
    const float* ff2_ln_g   = (const float*)d_in[7];
    const float* ff2_ln_b   = (const float*)d_in[8];
    const float* ff2_w1     = (const float*)d_in[9];
    const float* ff2_b1     = (const float*)d_in[10];
    const float* ff2_w2     = (const float*)d_in[11];
    const float* ff2_b2     = (const float*)d_in[12];
    const float* wq         = (const float*)d_in[13];
    const float* bq         = (const float*)d_in[14];
    const float* wk         = (const float*)d_in[15];
    const float* bk         = (const float*)d_in[16];
    const float* wv         = (const float*)d_in[17];
    const float* bv         = (const float*)d_in[18];
    const float* conv_ln_g  = (const float*)d_in[19];
    const float* conv_ln_b  = (const float*)d_in[20];
    const float* conv_pw1_w = (const float*)d_in[21];
    const float* conv_pw1_b = (const float*)d_in[22];
    const float* conv_dw_w  = (const float*)d_in[23];
    const float* conv_dw_b  = (const float*)d_in[24];
    const float* conv_bn_g  = (const float*)d_in[25];
    const float* conv_bn_b  = (const float*)d_in[26];
    const float* conv_pw2_w = (const float*)d_in[27];
    const float* conv_pw2_b = (const float*)d_in[28];
    const float* final_ln_g = (const float*)d_in[29];
    const float* final_ln_b = (const float*)d_in[30];

    __half *xn, *h16, *ff, *cv;
    float *h, *q, *k, *v, *cg, *pspill;
    __half *ff1w1t, *ff1w2t, *ff2w1t, *ff2w2t, *wqt, *wkt, *wvt, *pw1t, *pw2t;
    cudaGetSymbolAddress((void**)&xn,  g_xn);
    cudaGetSymbolAddress((void**)&h,   g_h);
    cudaGetSymbolAddress((void**)&h16, g_h16);
    cudaGetSymbolAddress((void**)&ff,  g_ff);
    cudaGetSymbolAddress((void**)&q,   g_q);
    cudaGetSymbolAddress((void**)&k,   g_k);
    cudaGetSymbolAddress((void**)&v,   g_v);
    cudaGetSymbolAddress((void**)&cg,  g_cg);
    cudaGetSymbolAddress((void**)&cv,  g_cv);
    cudaGetSymbolAddress((void**)&pspill, g_probs_spill);
    cudaGetSymbolAddress((void**)&ff1w1t, g_ff1w1t);
    cudaGetSymbolAddress((void**)&ff1w2t, g_ff1w2t);
    cudaGetSymbolAddress((void**)&ff2w1t, g_ff2w1t);
    cudaGetSymbolAddress((void**)&ff2w2t, g_ff2w2t);
    cudaGetSymbolAddress((void**)&wqt, g_wqt);
    cudaGetSymbolAddress((void**)&wkt, g_wkt);
    cudaGetSymbolAddress((void**)&wvt, g_wvt);
    cudaGetSymbolAddress((void**)&pw1t, g_pw1t);
    cudaGetSymbolAddress((void**)&pw2t, g_pw2t);

    float* out_main  = (float*)d_out;
    float* out_probs = (out_size >= OUT_ELEMS + PROB_ELEMS)
                         ? (float*)d_out + OUT_ELEMS : pspill;

    dim3 trb(32, 8);
    // weight transposes + fp16 convert (w[K][N] -> wt[N][K])
    transpose_h_kernel<<<tr_grid(DMODEL, FFDIM), trb>>>(ff1_w1, ff1w1t, DMODEL, FFDIM);
    transpose_h_kernel<<<tr_grid(FFDIM, DMODEL), trb>>>(ff1_w2, ff1w2t, FFDIM, DMODEL);
    transpose_h_kernel<<<tr_grid(DMODEL, FFDIM), trb>>>(ff2_w1, ff2w1t, DMODEL, FFDIM);
    transpose_h_kernel<<<tr_grid(FFDIM, DMODEL), trb>>>(ff2_w2, ff2w2t, FFDIM, DMODEL);
    transpose_h_kernel<<<tr_grid(DMODEL, DMODEL), trb>>>(wq, wqt, DMODEL, DMODEL);
    transpose_h_kernel<<<tr_grid(DMODEL, DMODEL), trb>>>(wk, wkt, DMODEL, DMODEL);
    transpose_h_kernel<<<tr_grid(DMODEL, DMODEL), trb>>>(wv, wvt, DMODEL, DMODEL);
    transpose_h_kernel<<<tr_grid(DMODEL, CEDIM), trb>>>(conv_pw1_w, pw1t, DMODEL, CEDIM);
    transpose_h_kernel<<<tr_grid(DMODEL, DMODEL), trb>>>(conv_pw2_w, pw2t, DMODEL, DMODEL);

    // ---- FF1: h = x + 0.5 * (swish(LN(x)@w1+b1) @ w2 + b2)  (h16 shadow)
    ln_kernel<<<NTOK, 256>>>(x, ff1_ln_g, ff1_ln_b, xn);
    gemm_h<1><<<gemm_grid(NTOK, FFDIM), 256>>>(xn, ff1w1t, ff1_b1, nullptr, 0.f,
                                               nullptr, ff, nullptr, NTOK, FFDIM, DMODEL);
    gemm_h<2><<<gemm_grid(NTOK, DMODEL), 256>>>(ff, ff1w2t, ff1_b2, x, 0.5f,
                                                h, nullptr, h16, NTOK, DMODEL, FFDIM);

    // ---- attention (q/k/v fp32 outs from fp16 GEMM)
    {
        QKVArgs args;
        args.wt[0] = wqt; args.wt[1] = wkt; args.wt[2] = wvt;
        args.b[0] = bq;   args.b[1] = bk;   args.b[2] = bv;
        args.o[0] = q;    args.o[1] = k;    args.o[2] = v;
        dim3 grid(DMODEL / 128, NTOK / 128, 3);
        gemm_h_qkv<<<grid, 256>>>(args, h16, NTOK, DMODEL, DMODEL);
    }
    attn_kernel<<<NTOK, 256>>>(q, k, v, h, out_probs);

    // ---- conv module
    ln_kernel<<<NTOK, 256>>>(h, conv_ln_g, conv_ln_b, xn);
    gemm_h<0><<<gemm_grid(NTOK, CEDIM), 256>>>(xn, pw1t, conv_pw1_b, nullptr, 0.f,
                                               cg, nullptr, nullptr, NTOK, CEDIM, DMODEL);
    {
        dim3 grid(DMODEL / DW_CH, NTOK / DW_TOK);
        glu_dwconv_kernel<<<grid, 256>>>(cg, conv_dw_w, conv_dw_b,
                                         conv_bn_g, conv_bn_b, cv);
    }
    gemm_h<2><<<gemm_grid(NTOK, DMODEL), 256>>>(cv, pw2t, conv_pw2_b, h, 1.0f,
                                                h, nullptr, nullptr, NTOK, DMODEL, DMODEL);

    // ---- FF2
    ln_kernel<<<NTOK, 256>>>(h, ff2_ln_g, ff2_ln_b, xn);
    gemm_h<1><<<gemm_grid(NTOK, FFDIM), 256>>>(xn, ff2w1t, ff2_b1, nullptr, 0.f,
                                               nullptr, ff, nullptr, NTOK, FFDIM, DMODEL);
    gemm_h<2><<<gemm_grid(NTOK, DMODEL), 256>>>(ff, ff2w2t, ff2_b2, h, 0.5f,
                                                h, nullptr, nullptr, NTOK, DMODEL, FFDIM);

    // ---- final LN -> out
    ln_f32_kernel<<<NTOK, 256>>>(h, final_ln_g, final_ln_b, out_main);
}

// round 9
// speedup vs baseline: 5.7324x; 1.1778x over previous
#include <cuda_runtime.h>
#include <cuda_fp16.h>
#include <math.h>
#include <stdint.h>

// ----------------------------------------------------------------------------
// ConformerBlock: B=4, T=1024, D=512, H=8, DH=64, W1=32, WB=65, FF=2048,
// CE=1024, KS=31.
// GEMMs: fp16 mma.sync m16n8k16 (fp32 accum), cp.async 3-stage BK=32,
// ldmatrix fragments, weights pre-transposed+converted fp16 n-major
// (single batched transpose launch). LN: warp-per-row. Attention: smem-tiled
// k/v + butterfly reduce-scatter. Conv: fused GLU+depthwise.
// ----------------------------------------------------------------------------

#define NTOK   4096          // B*T
#define DMODEL 512
#define TSEQ   1024
#define NHEAD  8
#define DHEAD  64
#define WB     65
#define FFDIM  2048
#define CEDIM  1024
#define KSIZE  31
#define OUT_ELEMS   (NTOK * DMODEL)          // 2097152
#define PROB_ELEMS  (NTOK * NHEAD * WB)      // 2129920

// ---- scratch (static device memory; no allocations allowed) ----
__device__ __align__(16) __half g_xn [NTOK * DMODEL];
__device__ __align__(16) float  g_h  [NTOK * DMODEL];
__device__ __align__(16) __half g_h16[NTOK * DMODEL];
__device__ __align__(16) __half g_ff [NTOK * FFDIM];
__device__ __align__(16) float  g_q  [NTOK * DMODEL];
__device__ __align__(16) float  g_k  [NTOK * DMODEL];
__device__ __align__(16) float  g_v  [NTOK * DMODEL];
__device__ __align__(16) float  g_cg [NTOK * CEDIM];
__device__ __align__(16) __half g_cv [NTOK * DMODEL];
__device__ __align__(16) float  g_probs_spill[PROB_ELEMS];

// transposed fp16 weights (n-major, [N][K])
__device__ __align__(16) __half g_ff1w1t[FFDIM * DMODEL];
__device__ __align__(16) __half g_ff1w2t[DMODEL * FFDIM];
__device__ __align__(16) __half g_ff2w1t[FFDIM * DMODEL];
__device__ __align__(16) __half g_ff2w2t[DMODEL * FFDIM];
__device__ __align__(16) __half g_wqt[DMODEL * DMODEL];
__device__ __align__(16) __half g_wkt[DMODEL * DMODEL];
__device__ __align__(16) __half g_wvt[DMODEL * DMODEL];
__device__ __align__(16) __half g_pw1t[CEDIM * DMODEL];
__device__ __align__(16) __half g_pw2t[DMODEL * DMODEL];

// ---------------------------------------------------------------- helpers
__device__ __forceinline__ float warp_sum(float v) {
    #pragma unroll
    for (int o = 16; o > 0; o >>= 1) v += __shfl_xor_sync(0xffffffffu, v, o);
    return v;
}
__device__ __forceinline__ float warp_max(float v) {
    #pragma unroll
    for (int o = 16; o > 0; o >>= 1) v = fmaxf(v, __shfl_xor_sync(0xffffffffu, v, o));
    return v;
}
__device__ __forceinline__ float swishf(float x) {
    return x / (1.0f + expf(-x));
}
__device__ __forceinline__ void mma_f16(float c[4], const uint32_t a[4], const uint32_t b[2]) {
    asm volatile(
        "mma.sync.aligned.m16n8k16.row.col.f32.f16.f16.f32 "
        "{%0,%1,%2,%3}, {%4,%5,%6,%7}, {%8,%9}, {%0,%1,%2,%3};"
        : "+f"(c[0]), "+f"(c[1]), "+f"(c[2]), "+f"(c[3])
        : "r"(a[0]), "r"(a[1]), "r"(a[2]), "r"(a[3]), "r"(b[0]), "r"(b[1]));
}
__device__ __forceinline__ void ldsm4(uint32_t& r0, uint32_t& r1, uint32_t& r2, uint32_t& r3,
                                      uint32_t addr) {
    asm volatile("ldmatrix.sync.aligned.m8n8.x4.shared.b16 {%0,%1,%2,%3}, [%4];"
                 : "=r"(r0), "=r"(r1), "=r"(r2), "=r"(r3) : "r"(addr));
}
__device__ __forceinline__ void cp16(uint32_t dst_smem, const void* src) {
    asm volatile("cp.async.cg.shared.global [%0], [%1], 16;"
                 :: "r"(dst_smem), "l"(src));
}
__device__ __forceinline__ void cp_commit() {
    asm volatile("cp.async.commit_group;");
}
__device__ __forceinline__ void cp_wait1() {
    asm volatile("cp.async.wait_group 1;");
}

// ---------------------------------------------------------------- batched transpose
// out[C][R] (fp16) = in[R][C]^T for 9 weight matrices in ONE launch.
struct TrJob { const float* src; __half* dst; int R; int C; int tstart; };
struct TrJobs { TrJob j[9]; };

__global__ void transpose_all_kernel(TrJobs J) {
    int t = blockIdx.x;
    int ji = 0;
    #pragma unroll
    for (int i = 1; i < 9; i++) if (t >= J.j[i].tstart) ji = i;
    const float* src = J.j[ji].src;
    __half* dst = J.j[ji].dst;
    int R = J.j[ji].R, C = J.j[ji].C;
    int local = t - J.j[ji].tstart;
    int tilesX = C >> 5;
    int bx = (local % tilesX) << 5;
    int by = (local / tilesX) << 5;

    __shared__ float tile[32][33];
    int tx = threadIdx.x, ty = threadIdx.y;   // 32 x 8
    #pragma unroll
    for (int i = 0; i < 32; i += 8)
        tile[ty + i][tx] = src[(size_t)(by + ty + i) * C + bx + tx];
    __syncthreads();
    #pragma unroll
    for (int i = 0; i < 32; i += 8)
        dst[(size_t)(bx + ty + i) * R + by + tx] = __float2half_rn(tile[tx][ty + i]);
}

// ---------------------------------------------------------------- fp16 GEMM
// (unchanged from R8) C = epilogue(A @ Bt^T + bias)
template <int MODE>
__device__ __forceinline__
void gemm_body(const __half* __restrict__ A, const __half* __restrict__ Bt,
               const float* __restrict__ bias, const float* __restrict__ res,
               float scale, float* __restrict__ Cf, __half* __restrict__ Ch,
               __half* __restrict__ C2,
               int M, int N, int K, int bm, int bn) {
    __shared__ __align__(16) uint32_t As[3][128][16];
    __shared__ __align__(16) uint32_t Bs[3][128][16];

    int tid  = threadIdx.x;
    int lane = tid & 31, wid = tid >> 5;
    int g = lane >> 2, tg = lane & 3;
    int m0w = (wid >> 1) * 32;
    int n0w = (wid & 1) * 64;

    int row0 = tid >> 2, c0 = tid & 3;
    int row1 = row0 + 64;
    int off0 = row0 * 16 + (c0 ^ ((row0 >> 1) & 3)) * 4;
    int off1 = row1 * 16 + (c0 ^ ((row1 >> 1) & 3)) * 4;

    const __half* a0src = A  + (size_t)(bm + row0) * K + c0 * 8;
    const __half* a1src = A  + (size_t)(bm + row1) * K + c0 * 8;
    const __half* b0src = Bt + (size_t)(bn + row0) * K + c0 * 8;
    const __half* b1src = Bt + (size_t)(bn + row1) * K + c0 * 8;

    uint32_t sA = (uint32_t)__cvta_generic_to_shared(&As[0][0][0]);
    uint32_t sB = (uint32_t)__cvta_generic_to_shared(&Bs[0][0][0]);
    const int ST = 128 * 16 * 4;

    int st  = lane >> 3;
    int rIn = lane & 7;
    int am  = m0w + (st & 1) * 8 + rIn;
    int an0 = n0w + (st & 1) * 8 + rIn;
    int cadd = st >> 1;

    float acc[2][8][4];
    #pragma unroll
    for (int mt = 0; mt < 2; mt++)
        #pragma unroll
        for (int nt = 0; nt < 8; nt++)
            #pragma unroll
            for (int i = 0; i < 4; i++) acc[mt][nt][i] = 0.0f;

    cp16(sA + 0 * ST + off0 * 4, a0src);
    cp16(sA + 0 * ST + off1 * 4, a1src);
    cp16(sB + 0 * ST + off0 * 4, b0src);
    cp16(sB + 0 * ST + off1 * 4, b1src);
    cp_commit();
    cp16(sA + 1 * ST + off0 * 4, a0src + 32);
    cp16(sA + 1 * ST + off1 * 4, a1src + 32);
    cp16(sB + 1 * ST + off0 * 4, b0src + 32);
    cp16(sB + 1 * ST + off1 * 4, b1src + 32);
    cp_commit();

    int niter = K / 32;
    int p = 0;
    for (int it = 0; it < niter; it++) {
        cp_wait1();
        __syncthreads();

        int kf = (it + 2) * 32;
        if (kf < K) {
            int pf = p + 2; if (pf >= 3) pf -= 3;
            cp16(sA + pf * ST + off0 * 4, a0src + kf);
            cp16(sA + pf * ST + off1 * 4, a1src + kf);
            cp16(sB + pf * ST + off0 * 4, b0src + kf);
            cp16(sB + pf * ST + off1 * 4, b1src + kf);
        }
        cp_commit();

        uint32_t stA = sA + p * ST;
        uint32_t stB = sB + p * ST;
        #pragma unroll
        for (int ks = 0; ks < 2; ks++) {
            int kkc = ks * 2;
            uint32_t af[2][4], bf[8][2];
            #pragma unroll
            for (int mt = 0; mt < 2; mt++) {
                int row = am + mt * 16;
                int c = (kkc + cadd) ^ ((row >> 1) & 3);
                uint32_t ad = stA + (row * 16 + c * 4) * 4;
                ldsm4(af[mt][0], af[mt][1], af[mt][2], af[mt][3], ad);
            }
            #pragma unroll
            for (int pp = 0; pp < 4; pp++) {
                int row = an0 + pp * 16;
                int c = (kkc + cadd) ^ ((row >> 1) & 3);
                uint32_t bd = stB + (row * 16 + c * 4) * 4;
                ldsm4(bf[2 * pp][0], bf[2 * pp + 1][0], bf[2 * pp][1], bf[2 * pp + 1][1], bd);
            }
            #pragma unroll
            for (int mt = 0; mt < 2; mt++)
                #pragma unroll
                for (int nt = 0; nt < 8; nt++)
                    mma_f16(acc[mt][nt], af[mt], bf[nt]);
        }
        p++; if (p >= 3) p = 0;
    }

    #pragma unroll
    for (int mt = 0; mt < 2; mt++) {
        int row0e = bm + m0w + mt * 16 + g;
        #pragma unroll
        for (int nt = 0; nt < 8; nt++) {
            int col = bn + n0w + nt * 8 + tg * 2;
            float bb0 = bias[col], bb1 = bias[col + 1];
            float v0 = acc[mt][nt][0] + bb0;
            float v1 = acc[mt][nt][1] + bb1;
            float v2 = acc[mt][nt][2] + bb0;
            float v3 = acc[mt][nt][3] + bb1;
            if (MODE == 1) {
                v0 = swishf(v0); v1 = swishf(v1); v2 = swishf(v2); v3 = swishf(v3);
                *(__half2*)(Ch + (size_t)row0e * N + col)       = __floats2half2_rn(v0, v1);
                *(__half2*)(Ch + (size_t)(row0e + 8) * N + col) = __floats2half2_rn(v2, v3);
            } else {
                if (MODE == 2) {
                    const float* r0p = res + (size_t)row0e * N + col;
                    const float* r1p = res + (size_t)(row0e + 8) * N + col;
                    v0 = r0p[0] + scale * v0;
                    v1 = r0p[1] + scale * v1;
                    v2 = r1p[0] + scale * v2;
                    v3 = r1p[1] + scale * v3;
                }
                *(float2*)(Cf + (size_t)row0e * N + col)       = make_float2(v0, v1);
                *(float2*)(Cf + (size_t)(row0e + 8) * N + col) = make_float2(v2, v3);
                if (MODE == 2 && C2 != nullptr) {
                    *(__half2*)(C2 + (size_t)row0e * N + col)       = __floats2half2_rn(v0, v1);
                    *(__half2*)(C2 + (size_t)(row0e + 8) * N + col) = __floats2half2_rn(v2, v3);
                }
            }
        }
    }
}

template <int MODE>
__global__ __launch_bounds__(256, 2)
void gemm_h(const __half* __restrict__ A, const __half* __restrict__ Bt,
            const float* __restrict__ bias, const float* __restrict__ res,
            float scale, float* __restrict__ Cf, __half* __restrict__ Ch,
            __half* __restrict__ C2, int M, int N, int K) {
    gemm_body<MODE>(A, Bt, bias, res, scale, Cf, Ch, C2, M, N, K,
                    blockIdx.y * 128, blockIdx.x * 128);
}

struct QKVArgs {
    const __half* wt[3];
    const float* b[3];
    float* o[3];
};

__global__ __launch_bounds__(256, 2)
void gemm_h_qkv(QKVArgs args, const __half* __restrict__ A, int M, int N, int K) {
    int z = blockIdx.z;
    gemm_body<0>(A, args.wt[z], args.b[z], nullptr, 0.0f, args.o[z], nullptr, nullptr,
                 M, N, K, blockIdx.y * 128, blockIdx.x * 128);
}

// ---------------------------------------------------------------- LayerNorm (warp/row)
// 8 warps/block, each warp owns one 512-elem row; no block barriers.
__global__ __launch_bounds__(256)
void ln_h_kernel(const float* __restrict__ x, const float* __restrict__ g,
                 const float* __restrict__ b, __half* __restrict__ out) {
    int row = blockIdx.x * 8 + (threadIdx.x >> 5);
    int lane = threadIdx.x & 31;
    const float4* xr = (const float4*)(x + (size_t)row * DMODEL);
    float4 vv[4];
    float s = 0.0f, qq = 0.0f;
    #pragma unroll
    for (int j = 0; j < 4; j++) {
        vv[j] = xr[lane + 32 * j];
        s  += vv[j].x + vv[j].y + vv[j].z + vv[j].w;
        qq += vv[j].x * vv[j].x + vv[j].y * vv[j].y + vv[j].z * vv[j].z + vv[j].w * vv[j].w;
    }
    s = warp_sum(s);
    qq = warp_sum(qq);
    float mean = s * (1.0f / DMODEL);
    float var  = qq * (1.0f / DMODEL) - mean * mean;
    float inv  = rsqrtf(var + 1e-5f);
    __half2* orow = (__half2*)(out + (size_t)row * DMODEL);
    #pragma unroll
    for (int j = 0; j < 4; j++) {
        int f = lane + 32 * j;
        float4 g4 = ((const float4*)g)[f];
        float4 b4 = ((const float4*)b)[f];
        float o0 = (vv[j].x - mean) * inv * g4.x + b4.x;
        float o1 = (vv[j].y - mean) * inv * g4.y + b4.y;
        float o2 = (vv[j].z - mean) * inv * g4.z + b4.z;
        float o3 = (vv[j].w - mean) * inv * g4.w + b4.w;
        orow[f * 2]     = __floats2half2_rn(o0, o1);
        orow[f * 2 + 1] = __floats2half2_rn(o2, o3);
    }
}

__global__ __launch_bounds__(256)
void ln_f32_kernel(const float* __restrict__ x, const float* __restrict__ g,
                   const float* __restrict__ b, float* __restrict__ out) {
    int row = blockIdx.x * 8 + (threadIdx.x >> 5);
    int lane = threadIdx.x & 31;
    const float4* xr = (const float4*)(x + (size_t)row * DMODEL);
    float4 vv[4];
    float s = 0.0f, qq = 0.0f;
    #pragma unroll
    for (int j = 0; j < 4; j++) {
        vv[j] = xr[lane + 32 * j];
        s  += vv[j].x + vv[j].y + vv[j].z + vv[j].w;
        qq += vv[j].x * vv[j].x + vv[j].y * vv[j].y + vv[j].z * vv[j].z + vv[j].w * vv[j].w;
    }
    s = warp_sum(s);
    qq = warp_sum(qq);
    float mean = s * (1.0f / DMODEL);
    float var  = qq * (1.0f / DMODEL) - mean * mean;
    float inv  = rsqrtf(var + 1e-5f);
    float4* orow = (float4*)(out + (size_t)row * DMODEL);
    #pragma unroll
    for (int j = 0; j < 4; j++) {
        int f = lane + 32 * j;
        float4 g4 = ((const float4*)g)[f];
        float4 b4 = ((const float4*)b)[f];
        float4 o;
        o.x = (vv[j].x - mean) * inv * g4.x + b4.x;
        o.y = (vv[j].y - mean) * inv * g4.y + b4.y;
        o.z = (vv[j].z - mean) * inv * g4.z + b4.z;
        o.w = (vv[j].w - mean) * inv * g4.w + b4.w;
        orow[f] = o;
    }
}

// ---------------------------------------------------------------- attention (smem-tiled)
// block = (16 tokens) x (1 head). k/v tile (80 pos x 64 ch) staged in smem once.
#define AT_TOK 16
#define AT_ROWS (AT_TOK + WB - 1)    // 80
__global__ __launch_bounds__(256)
void attn_kernel(const float* __restrict__ q, const float* __restrict__ k,
                 const float* __restrict__ v, float* __restrict__ h,
                 float* __restrict__ probs) {
    __shared__ float ks[AT_ROWS][66];
    __shared__ float vs[AT_ROWS][66];
    __shared__ float sc[8][WB + 3];

    int head = blockIdx.y;
    int t0g  = blockIdx.x * AT_TOK;        // global token start
    int t0   = t0g & (TSEQ - 1);
    int bstart = t0g - t0;
    int tid  = threadIdx.x;

    // stage k/v rows [t0-32, t0+63]
    for (int i = tid; i < AT_ROWS * 32; i += 256) {
        int r  = i >> 5;
        int c2 = i & 31;
        int pos = t0 - 32 + r;
        float2 kv = make_float2(0.0f, 0.0f), vv2 = make_float2(0.0f, 0.0f);
        if (pos >= 0 && pos < TSEQ) {
            size_t gbase = (size_t)(bstart + pos) * DMODEL + head * DHEAD + c2 * 2;
            kv  = *(const float2*)&k[gbase];
            vv2 = *(const float2*)&v[gbase];
        }
        *(float2*)&ks[r][c2 * 2] = kv;
        *(float2*)&vs[r][c2 * 2] = vv2;
    }
    __syncthreads();

    int warpid = tid >> 5, lane = tid & 31;
    int d0 = lane * 2;
    float* scrow = sc[warpid];

    #pragma unroll
    for (int ti = 0; ti < AT_TOK / 8; ti++) {
        int t = t0 + warpid * (AT_TOK / 8) + ti;
        int row = bstart + t;
        int base = row * DMODEL + head * DHEAD;
        int lbase = t - t0;                   // 0..15

        float q0 = q[base + d0] * 0.125f;
        float q1 = q[base + d0 + 1] * 0.125f;

        float sgrp[2];
        #pragma unroll
        for (int gsel = 0; gsel < 2; gsel++) {
            int wb = gsel * 32;
            float acc[32];
            #pragma unroll
            for (int w = 0; w < 32; w++) {
                float2 kv = *(const float2*)&ks[lbase + wb + w][d0];
                acc[w] = q0 * kv.x + q1 * kv.y;
            }
            int n = 32;
            #pragma unroll
            for (int off = 16; off >= 1; off >>= 1) {
                bool upper = (lane & off) != 0;
                #pragma unroll
                for (int j = 0; j < 16; j++) {
                    if (j < n / 2) {
                        float send = upper ? acc[j] : acc[j + n / 2];
                        float recv = __shfl_xor_sync(0xffffffffu, send, off);
                        acc[j] = (upper ? acc[j + n / 2] : acc[j]) + recv;
                    }
                }
                n >>= 1;
            }
            int posW = t + wb + lane - 32;
            sgrp[gsel] = (posW >= 0 && posW < TSEQ) ? acc[0] : -1e9f;
        }

        float s64;
        {
            float2 kv = *(const float2*)&ks[lbase + 64][d0];
            float p = q0 * kv.x + q1 * kv.y;
            p = warp_sum(p);
            s64 = (t + 32 < TSEQ) ? p : -1e9f;
        }

        float m = fmaxf(fmaxf(sgrp[0], sgrp[1]), s64);
        m = warp_max(m);
        float e0 = expf(sgrp[0] - m);
        float e1 = expf(sgrp[1] - m);
        float e64 = expf(s64 - m);
        float sum = warp_sum(e0 + e1) + e64;
        float inv = 1.0f / sum;
        float p0 = e0 * inv, p1 = e1 * inv, p64 = e64 * inv;

        float* prow = probs + ((size_t)row * NHEAD + head) * WB;
        scrow[lane] = p0;
        scrow[lane + 32] = p1;
        prow[lane] = p0;
        prow[lane + 32] = p1;
        if (lane == 0) { scrow[64] = p64; prow[64] = p64; }
        __syncwarp();

        float a0 = 0.0f, a1 = 0.0f;
        for (int w = 0; w < WB; w++) {
            int pos = t + w - 32;
            if (pos >= 0 && pos < TSEQ) {
                float pr = scrow[w];
                float2 vv2 = *(const float2*)&vs[lbase + w][d0];
                a0 = fmaf(pr, vv2.x, a0);
                a1 = fmaf(pr, vv2.y, a1);
            }
        }
        h[base + d0]     += a0;
        h[base + d0 + 1] += a1;
        __syncwarp();
    }
}

// ---------------------------------------- fused GLU + depthwise conv + BN + swish
#define DW_TOK 64
#define DW_CH  128
__global__ __launch_bounds__(256)
void glu_dwconv_kernel(const float* __restrict__ cg,
                       const float* __restrict__ dw_w,
                       const float* __restrict__ dw_b,
                       const float* __restrict__ bn_g,
                       const float* __restrict__ bn_b,
                       __half* __restrict__ out) {
    __shared__ float s[DW_TOK + KSIZE - 1][DW_CH];
    int ct = blockIdx.x * DW_CH;
    int tt = blockIdx.y * DW_TOK;
    int t0 = tt & (TSEQ - 1);
    int bstart = tt - t0;
    int tid = threadIdx.x;

    for (int i = tid; i < (DW_TOK + KSIZE - 1) * DW_CH; i += 256) {
        int r = i >> 7;
        int c = i & (DW_CH - 1);
        int pos = t0 + r - 15;
        float val = 0.0f;
        if (pos >= 0 && pos < TSEQ) {
            const float* cgrow = cg + (size_t)(bstart + pos) * CEDIM;
            float a = cgrow[ct + c];
            float gate = cgrow[DMODEL + ct + c];
            val = a / (1.0f + expf(-gate));
        }
        s[r][c] = val;
    }
    __syncthreads();

    int c = tid & (DW_CH - 1);
    int trow = tid >> 7;
    float wreg[KSIZE];
    #pragma unroll
    for (int j = 0; j < KSIZE; j++) wreg[j] = dw_w[j * DMODEL + ct + c];
    float bb = dw_b[ct + c];
    float bg = bn_g[ct + c] * rsqrtf(1.0f + 1e-5f);
    float bbn = bn_b[ct + c];

    #pragma unroll 4
    for (int i = 0; i < DW_TOK / 2; i++) {
        int lt = trow + 2 * i;
        float acc = 0.0f;
        #pragma unroll
        for (int j = 0; j < KSIZE; j++)
            acc = fmaf(s[lt + j][c], wreg[j], acc);
        acc += bb;
        float hx = acc * bg + bbn;
        out[(size_t)(tt + lt) * DMODEL + ct + c] = __float2half_rn(swishf(hx));
    }
}

// ---------------------------------------------------------------- launch
static inline dim3 gemm_grid(int M, int N) { return dim3(N / 128, M / 128); }

extern "C" void kernel_launch(void* const* d_in, const int* in_sizes, int n_in,
                              void* d_out, int out_size) {
    const float* x          = (const float*)d_in[0];
    const float* ff1_ln_g   = (const float*)d_in[1];
    const float* ff1_ln_b   = (const float*)d_in[2];
    const float* ff1_w1     = (const float*)d_in[3];
    const float* ff1_b1     = (const float*)d_in[4];
    const float* ff1_w2     = (const float*)d_in[5];
    const float* ff1_b2     = (const float*)d_in[6];
    const float* ff2_ln_g   = (const float*)d_in[7];
    const float* ff2_ln_b   = (const float*)d_in[8];
    const float* ff2_w1     = (const float*)d_in[9];
    const float* ff2_b1     = (const float*)d_in[10];
    const float* ff2_w2     = (const float*)d_in[11];
    const float* ff2_b2     = (const float*)d_in[12];
    const float* wq         = (const float*)d_in[13];
    const float* bq         = (const float*)d_in[14];
    const float* wk         = (const float*)d_in[15];
    const float* bk         = (const float*)d_in[16];
    const float* wv         = (const float*)d_in[17];
    const float* bv         = (const float*)d_in[18];
    const float* conv_ln_g  = (const float*)d_in[19];
    const float* conv_ln_b  = (const float*)d_in[20];
    const float* conv_pw1_w = (const float*)d_in[21];
    const float* conv_pw1_b = (const float*)d_in[22];
    const float* conv_dw_w  = (const float*)d_in[23];
    const float* conv_dw_b  = (const float*)d_in[24];
    const float* conv_bn_g  = (const float*)d_in[25];
    const float* conv_bn_b  = (const float*)d_in[26];
    const float* conv_pw2_w = (const float*)d_in[27];
    const float* conv_pw2_b = (const float*)d_in[28];
    const float* final_ln_g = (const float*)d_in[29];
    const float* final_ln_b = (const float*)d_in[30];

    __half *xn, *h16, *ff, *cv;
    float *h, *q, *k, *v, *cg, *pspill;
    __half *ff1w1t, *ff1w2t, *ff2w1t, *ff2w2t, *wqt, *wkt, *wvt, *pw1t, *pw2t;
    cudaGetSymbolAddress((void**)&xn,  g_xn);
    cudaGetSymbolAddress((void**)&h,   g_h);
    cudaGetSymbolAddress((void**)&h16, g_h16);
    cudaGetSymbolAddress((void**)&ff,  g_ff);
    cudaGetSymbolAddress((void**)&q,   g_q);
    cudaGetSymbolAddress((void**)&k,   g_k);
    cudaGetSymbolAddress((void**)&v,   g_v);
    cudaGetSymbolAddress((void**)&cg,  g_cg);
    cudaGetSymbolAddress((void**)&cv,  g_cv);
    cudaGetSymbolAddress((void**)&pspill, g_probs_spill);
    cudaGetSymbolAddress((void**)&ff1w1t, g_ff1w1t);
    cudaGetSymbolAddress((void**)&ff1w2t, g_ff1w2t);
    cudaGetSymbolAddress((void**)&ff2w1t, g_ff2w1t);
    cudaGetSymbolAddress((void**)&ff2w2t, g_ff2w2t);
    cudaGetSymbolAddress((void**)&wqt, g_wqt);
    cudaGetSymbolAddress((void**)&wkt, g_wkt);
    cudaGetSymbolAddress((void**)&wvt, g_wvt);
    cudaGetSymbolAddress((void**)&pw1t, g_pw1t);
    cudaGetSymbolAddress((void**)&pw2t, g_pw2t);

    float* out_main  = (float*)d_out;
    float* out_probs = (out_size >= OUT_ELEMS + PROB_ELEMS)
                         ? (float*)d_out + OUT_ELEMS : pspill;

    // ---- single batched transpose launch (9 weights -> fp16 n-major)
    {
        TrJobs J;
        auto setj = [&](int i, const float* s, __half* d, int R, int C, int ts) {
            J.j[i].src = s; J.j[i].dst = d; J.j[i].R = R; J.j[i].C = C; J.j[i].tstart = ts;
        };
        int ts = 0;
        setj(0, ff1_w1, ff1w1t, DMODEL, FFDIM, ts);  ts += (FFDIM/32)*(DMODEL/32);   // 1024
        setj(1, ff1_w2, ff1w2t, FFDIM, DMODEL, ts);  ts += (DMODEL/32)*(FFDIM/32);   // 1024
        setj(2, ff2_w1, ff2w1t, DMODEL, FFDIM, ts);  ts += (FFDIM/32)*(DMODEL/32);
        setj(3, ff2_w2, ff2w2t, FFDIM, DMODEL, ts);  ts += (DMODEL/32)*(FFDIM/32);
        setj(4, wq, wqt, DMODEL, DMODEL, ts);        ts += (DMODEL/32)*(DMODEL/32);  // 256
        setj(5, wk, wkt, DMODEL, DMODEL, ts);        ts += (DMODEL/32)*(DMODEL/32);
        setj(6, wv, wvt, DMODEL, DMODEL, ts);        ts += (DMODEL/32)*(DMODEL/32);
        setj(7, conv_pw1_w, pw1t, DMODEL, CEDIM, ts); ts += (CEDIM/32)*(DMODEL/32);  // 512
        setj(8, conv_pw2_w, pw2t, DMODEL, DMODEL, ts); ts += (DMODEL/32)*(DMODEL/32);
        transpose_all_kernel<<<ts, dim3(32, 8)>>>(J);
    }

    // ---- FF1: h = x + 0.5 * (swish(LN(x)@w1+b1) @ w2 + b2)  (h16 shadow)
    ln_h_kernel<<<NTOK / 8, 256>>>(x, ff1_ln_g, ff1_ln_b, xn);
    gemm_h<1><<<gemm_grid(NTOK, FFDIM), 256>>>(xn, ff1w1t, ff1_b1, nullptr, 0.f,
                                               nullptr, ff, nullptr, NTOK, FFDIM, DMODEL);
    gemm_h<2><<<gemm_grid(NTOK, DMODEL), 256>>>(ff, ff1w2t, ff1_b2, x, 0.5f,
                                                h, nullptr, h16, NTOK, DMODEL, FFDIM);

    // ---- attention
    {
        QKVArgs args;
        args.wt[0] = wqt; args.wt[1] = wkt; args.wt[2] = wvt;
        args.b[0] = bq;   args.b[1] = bk;   args.b[2] = bv;
        args.o[0] = q;    args.o[1] = k;    args.o[2] = v;
        dim3 grid(DMODEL / 128, NTOK / 128, 3);
        gemm_h_qkv<<<grid, 256>>>(args, h16, NTOK, DMODEL, DMODEL);
    }
    attn_kernel<<<dim3(NTOK / AT_TOK, NHEAD), 256>>>(q, k, v, h, out_probs);

    // ---- conv module
    ln_h_kernel<<<NTOK / 8, 256>>>(h, conv_ln_g, conv_ln_b, xn);
    gemm_h<0><<<gemm_grid(NTOK, CEDIM), 256>>>(xn, pw1t, conv_pw1_b, nullptr, 0.f,
                                               cg, nullptr, nullptr, NTOK, CEDIM, DMODEL);
    {
        dim3 grid(DMODEL / DW_CH, NTOK / DW_TOK);
        glu_dwconv_kernel<<<grid, 256>>>(cg, conv_dw_w, conv_dw_b,
                                         conv_bn_g, conv_bn_b, cv);
    }
    gemm_h<2><<<gemm_grid(NTOK, DMODEL), 256>>>(cv, pw2t, conv_pw2_b, h, 1.0f,
                                                h, nullptr, nullptr, NTOK, DMODEL, DMODEL);

    // ---- FF2
    ln_h_kernel<<<NTOK / 8, 256>>>(h, ff2_ln_g, ff2_ln_b, xn);
    gemm_h<1><<<gemm_grid(NTOK, FFDIM), 256>>>(xn, ff2w1t, ff2_b1, nullptr, 0.f,
                                               nullptr, ff, nullptr, NTOK, FFDIM, DMODEL);
    gemm_h<2><<<gemm_grid(NTOK, DMODEL), 256>>>(ff, ff2w2t, ff2_b2, h, 0.5f,
                                                h, nullptr, nullptr, NTOK, DMODEL, FFDIM);

    // ---- final LN -> out
    ln_f32_kernel<<<NTOK / 8, 256>>>(h, final_ln_g, final_ln_b, out_main);
}